// round 1
// baseline (speedup 1.0000x reference)
#include <cuda_runtime.h>
#include <math.h>

// ---------------------------------------------------------------------------
// TimeSformer block: temporal MHSA + spatial Linformer + GELU FFN (fp32)
// Decomposed into: gather kernels, a generic strided-batched tiled SGEMM
// (with fused epilogues: scale / bias+gelu / bias+residual / residual),
// and a row-softmax kernel.
// ---------------------------------------------------------------------------

#define FRAMES_C  256
#define PATCHES_C 64
#define DIM_C     512
#define HEADS_C   8
#define DH_C      64
#define DFF_C     1024
#define KLIN_C    128
#define NT_T      257            // temporal seq len (1 + FRAMES)
#define NT_S      65             // spatial seq len  (1 + PATCHES)
#define BT_C      64             // temporal batch  (= PATCHES)
#define BS_C      256            // spatial batch   (= FRAMES)

// ------------------------- scratch (device globals) ------------------------
__device__ float g_XT  [(size_t)BT_C * NT_T * DIM_C];          // (64,257,512)
__device__ float g_QKVT[(size_t)BT_C * NT_T * 3 * DIM_C];      // (64,257,1536)
__device__ float g_ST  [(size_t)BT_C * HEADS_C * NT_T * NT_T]; // (512,257,257)
__device__ float g_OT  [(size_t)BT_C * NT_T * DIM_C];          // (64,257,512) head-merged
__device__ float g_Y1  [(size_t)BT_C * NT_T * DIM_C];
__device__ float g_Z   [(size_t)BS_C * NT_S * DIM_C];          // (256,65,512)
__device__ float g_QKVS[(size_t)BS_C * NT_S * 3 * DIM_C];
__device__ float g_Et  [(size_t)KLIN_C * NT_S];                // E^T (128,65)
__device__ float g_KC  [(size_t)BS_C * HEADS_C * KLIN_C * DH_C];
__device__ float g_VC  [(size_t)BS_C * HEADS_C * KLIN_C * DH_C];
__device__ float g_SS  [(size_t)BS_C * HEADS_C * NT_S * KLIN_C];
__device__ float g_OS  [(size_t)BS_C * NT_S * DIM_C];
__device__ float g_Y2  [(size_t)BS_C * NT_S * DIM_C];
__device__ float g_H   [(size_t)BS_C * NT_S * DFF_C];

// ------------------------------- gathers -----------------------------------
__global__ void build_xt(const float* __restrict__ x) {
    long idx = (long)blockIdx.x * blockDim.x + threadIdx.x;
    const long total = (long)BT_C * NT_T * DIM_C;
    if (idx >= total) return;
    int d = (int)(idx % DIM_C);
    long r = idx / DIM_C;
    int t = (int)(r % NT_T);
    int p = (int)(r / NT_T);
    float v;
    if (t == 0) v = x[d];                                   // CLS
    else        v = x[(long)(1 + (t - 1) * PATCHES_C + p) * DIM_C + d];
    g_XT[idx] = v;
}

__global__ void build_z() {
    long idx = (long)blockIdx.x * blockDim.x + threadIdx.x;
    const long total = (long)BS_C * NT_S * DIM_C;
    if (idx >= total) return;
    int d = (int)(idx % DIM_C);
    long r = idx / DIM_C;
    int s = (int)(r % NT_S);
    int f = (int)(r / NT_S);
    float v;
    if (s == 0) v = g_Y1[(long)(f & 63) * NT_T * DIM_C + d];            // cls2[f%64]
    else        v = g_Y1[(long)(s - 1) * NT_T * DIM_C + (long)(1 + f) * DIM_C + d];
    g_Z[idx] = v;
}

__global__ void transpose_E(const float* __restrict__ E) {
    int i = blockIdx.x * blockDim.x + threadIdx.x;
    if (i >= KLIN_C * NT_S) return;
    int j = i % NT_S, kc = i / NT_S;
    g_Et[i] = E[j * KLIN_C + kc];
}

// ------------------------------- softmax -----------------------------------
__global__ void softmax_rows(float* __restrict__ S, int ncols) {
    long row = blockIdx.x;
    float* p = S + row * (long)ncols;
    int tid = threadIdx.x;
    __shared__ float red[128];
    float m = -1e30f;
    for (int c = tid; c < ncols; c += 128) m = fmaxf(m, p[c]);
    red[tid] = m; __syncthreads();
    for (int s = 64; s > 0; s >>= 1) { if (tid < s) red[tid] = fmaxf(red[tid], red[tid + s]); __syncthreads(); }
    m = red[0]; __syncthreads();
    float sum = 0.f;
    for (int c = tid; c < ncols; c += 128) { float e = expf(p[c] - m); p[c] = e; sum += e; }
    red[tid] = sum; __syncthreads();
    for (int s = 64; s > 0; s >>= 1) { if (tid < s) red[tid] += red[tid + s]; __syncthreads(); }
    float inv = 1.f / red[0];
    for (int c = tid; c < ncols; c += 128) p[c] *= inv;
}

// ------------------------- generic batched SGEMM ----------------------------
// C[e] = alpha * A[e] @ op(B[e])  (+ epilogue), e = o*NI + i,
// ptr[e] = base + o*so + i*si.
// TRB: B stored (N x K) row-major, computes A @ B^T.
// EPI: 0 none | 1 bias+exact-gelu | 2 bias+residual | 3 residual
template<int BM, int BN, int BK, int TM, int TN, bool TRB, int EPI>
__global__ void __launch_bounds__((BM / TM) * (BN / TN))
gemm_k(const float* __restrict__ A, const float* __restrict__ B,
       float* __restrict__ C, const float* __restrict__ bias,
       const float* __restrict__ R,
       int M, int N, int K, int lda, int ldb, int ldc,
       long soA, long siA, long soB, long siB, long soC, long siC,
       int NI, float alpha)
{
    constexpr int NTH = (BM / TM) * (BN / TN);
    __shared__ float As[BK][BM];
    __shared__ float Bs[BK][BN];

    int e = blockIdx.z;
    int o = e / NI, ii = e - o * NI;
    A += o * soA + (long)ii * siA;
    B += o * soB + (long)ii * siB;
    C += o * soC + (long)ii * siC;
    if (R) R += o * soC + (long)ii * siC;

    const int bm = blockIdx.y * BM;
    const int bn = blockIdx.x * BN;
    const int tid = threadIdx.x;
    const int tx = tid % (BN / TN);
    const int ty = tid / (BN / TN);

    float acc[TM][TN];
    #pragma unroll
    for (int m = 0; m < TM; m++)
        #pragma unroll
        for (int n = 0; n < TN; n++) acc[m][n] = 0.f;

    for (int k0 = 0; k0 < K; k0 += BK) {
        #pragma unroll
        for (int t = tid; t < BM * BK; t += NTH) {
            int r = t / BK, kk = t % BK;
            int gr = bm + r, gk = k0 + kk;
            As[kk][r] = (gr < M && gk < K) ? A[(long)gr * lda + gk] : 0.f;
        }
        if (!TRB) {
            #pragma unroll
            for (int t = tid; t < BK * BN; t += NTH) {
                int kk = t / BN, c = t % BN;
                int gk = k0 + kk, gc = bn + c;
                Bs[kk][c] = (gk < K && gc < N) ? B[(long)gk * ldb + gc] : 0.f;
            }
        } else {
            #pragma unroll
            for (int t = tid; t < BK * BN; t += NTH) {
                int c = t / BK, kk = t % BK;
                int gk = k0 + kk, gc = bn + c;
                Bs[kk][c] = (gk < K && gc < N) ? B[(long)gc * ldb + gk] : 0.f;
            }
        }
        __syncthreads();
        #pragma unroll
        for (int kk = 0; kk < BK; kk++) {
            float ra[TM], rb[TN];
            #pragma unroll
            for (int m = 0; m < TM; m++) ra[m] = As[kk][ty * TM + m];
            #pragma unroll
            for (int n = 0; n < TN; n++) rb[n] = Bs[kk][tx * TN + n];
            #pragma unroll
            for (int m = 0; m < TM; m++)
                #pragma unroll
                for (int n = 0; n < TN; n++) acc[m][n] += ra[m] * rb[n];
        }
        __syncthreads();
    }

    #pragma unroll
    for (int m = 0; m < TM; m++) {
        int gr = bm + ty * TM + m;
        if (gr >= M) continue;
        #pragma unroll
        for (int n = 0; n < TN; n++) {
            int gc = bn + tx * TN + n;
            if (gc >= N) continue;
            float v = acc[m][n] * alpha;
            if (EPI == 1) { v += bias[gc]; v = 0.5f * v * (1.f + erff(v * 0.70710678118654752f)); }
            else if (EPI == 2) { v += bias[gc] + R[(long)gr * ldc + gc]; }
            else if (EPI == 3) { v += R[(long)gr * ldc + gc]; }
            C[(long)gr * ldc + gc] = v;
        }
    }
}

// Config aliases
#define GEMM_BIG   gemm_k<128,128,8,8,8,false,0>
#define GEMM_BIG_R gemm_k<128,128,8,8,8,false,3>
#define GEMM_BIG_G gemm_k<128,128,8,8,8,false,1>
#define GEMM_BIG_BR gemm_k<128,128,8,8,8,false,2>
#define GEMM_SM    gemm_k<64,64,16,4,4,false,0>
#define GEMM_SM_T  gemm_k<64,64,16,4,4,true,0>

static inline dim3 g3(int N, int BN, int M, int BM, int Z) {
    return dim3((N + BN - 1) / BN, (M + BM - 1) / BM, Z);
}

extern "C" void kernel_launch(void* const* d_in, const int* in_sizes, int n_in,
                              void* d_out, int out_size) {
    const float* x      = (const float*)d_in[0];
    const float* Wqkv_t = (const float*)d_in[1];
    const float* Wo_t   = (const float*)d_in[2];
    const float* Wqkv_s = (const float*)d_in[3];
    const float* Wo_s   = (const float*)d_in[4];
    const float* E      = (const float*)d_in[5];
    const float* W1     = (const float*)d_in[6];
    const float* b1     = (const float*)d_in[7];
    const float* W2     = (const float*)d_in[8];
    const float* b2     = (const float*)d_in[9];
    float* out = (float*)d_out;

    float *XT, *QKVT, *ST, *OT, *Y1, *Z, *QKVS, *Et, *KC, *VC, *SS, *OS, *Y2, *H;
    cudaGetSymbolAddress((void**)&XT,   g_XT);
    cudaGetSymbolAddress((void**)&QKVT, g_QKVT);
    cudaGetSymbolAddress((void**)&ST,   g_ST);
    cudaGetSymbolAddress((void**)&OT,   g_OT);
    cudaGetSymbolAddress((void**)&Y1,   g_Y1);
    cudaGetSymbolAddress((void**)&Z,    g_Z);
    cudaGetSymbolAddress((void**)&QKVS, g_QKVS);
    cudaGetSymbolAddress((void**)&Et,   g_Et);
    cudaGetSymbolAddress((void**)&KC,   g_KC);
    cudaGetSymbolAddress((void**)&VC,   g_VC);
    cudaGetSymbolAddress((void**)&SS,   g_SS);
    cudaGetSymbolAddress((void**)&OS,   g_OS);
    cudaGetSymbolAddress((void**)&Y2,   g_Y2);
    cudaGetSymbolAddress((void**)&H,    g_H);

    const int MT = BT_C * NT_T;   // 16448
    const int MS = BS_C * NT_S;   // 16640

    // 1. gather -> XT (64,257,512)
    {
        long total = (long)BT_C * NT_T * DIM_C;
        build_xt<<<(unsigned)((total + 255) / 256), 256>>>(x);
    }
    // 2. QKV_T = XT @ Wqkv_t   (16448 x 1536 x 512)
    GEMM_BIG<<<g3(3 * DIM_C, 128, MT, 128, 1), 256>>>(
        XT, Wqkv_t, QKVT, nullptr, nullptr,
        MT, 3 * DIM_C, DIM_C, DIM_C, 3 * DIM_C, 3 * DIM_C,
        0, 0, 0, 0, 0, 0, 1, 1.f);
    // 3. S_T[b,h] = 0.125 * Q @ K^T   (512 batches, 257x257x64)
    GEMM_SM_T<<<g3(NT_T, 64, NT_T, 64, BT_C * HEADS_C), 256>>>(
        QKVT, QKVT + DIM_C, ST, nullptr, nullptr,
        NT_T, NT_T, DH_C, 3 * DIM_C, 3 * DIM_C, NT_T,
        (long)NT_T * 3 * DIM_C, DH_C, (long)NT_T * 3 * DIM_C, DH_C,
        (long)HEADS_C * NT_T * NT_T, (long)NT_T * NT_T,
        HEADS_C, 0.125f);
    // 4. softmax rows
    softmax_rows<<<BT_C * HEADS_C * NT_T, 128>>>(ST, NT_T);
    // 5. O_T[b,h] = S @ V   (257x64x257), head-merged output (64,257,512)
    GEMM_SM<<<g3(DH_C, 64, NT_T, 64, BT_C * HEADS_C), 256>>>(
        ST, QKVT + 2 * DIM_C, OT, nullptr, nullptr,
        NT_T, DH_C, NT_T, NT_T, 3 * DIM_C, DIM_C,
        (long)HEADS_C * NT_T * NT_T, (long)NT_T * NT_T,
        (long)NT_T * 3 * DIM_C, DH_C,
        (long)NT_T * DIM_C, DH_C,
        HEADS_C, 1.f);
    // 6. Y1 = O_T @ Wo_t + XT
    GEMM_BIG_R<<<g3(DIM_C, 128, MT, 128, 1), 256>>>(
        OT, Wo_t, Y1, nullptr, XT,
        MT, DIM_C, DIM_C, DIM_C, DIM_C, DIM_C,
        0, 0, 0, 0, 0, 0, 1, 1.f);
    // 7. gather -> Z (256,65,512)
    {
        long total = (long)BS_C * NT_S * DIM_C;
        build_z<<<(unsigned)((total + 255) / 256), 256>>>();
    }
    // 8. QKV_S = Z @ Wqkv_s
    GEMM_BIG<<<g3(3 * DIM_C, 128, MS, 128, 1), 256>>>(
        Z, Wqkv_s, QKVS, nullptr, nullptr,
        MS, 3 * DIM_C, DIM_C, DIM_C, 3 * DIM_C, 3 * DIM_C,
        0, 0, 0, 0, 0, 0, 1, 1.f);
    // 9. E^T
    transpose_E<<<(KLIN_C * NT_S + 255) / 256, 256>>>(E);
    // 10/11. K_c, V_c = E^T @ {K,V}   (2048 batches, 128x64x65)
    GEMM_SM<<<g3(DH_C, 64, KLIN_C, 64, BS_C * HEADS_C), 256>>>(
        Et, QKVS + DIM_C, KC, nullptr, nullptr,
        KLIN_C, DH_C, NT_S, NT_S, 3 * DIM_C, DH_C,
        0, 0, (long)NT_S * 3 * DIM_C, DH_C,
        (long)HEADS_C * KLIN_C * DH_C, (long)KLIN_C * DH_C,
        HEADS_C, 1.f);
    GEMM_SM<<<g3(DH_C, 64, KLIN_C, 64, BS_C * HEADS_C), 256>>>(
        Et, QKVS + 2 * DIM_C, VC, nullptr, nullptr,
        KLIN_C, DH_C, NT_S, NT_S, 3 * DIM_C, DH_C,
        0, 0, (long)NT_S * 3 * DIM_C, DH_C,
        (long)HEADS_C * KLIN_C * DH_C, (long)KLIN_C * DH_C,
        HEADS_C, 1.f);
    // 12. S_S = 0.125 * Q @ K_c^T   (2048 batches, 65x128x64)
    GEMM_SM_T<<<g3(KLIN_C, 64, NT_S, 64, BS_C * HEADS_C), 256>>>(
        QKVS, KC, SS, nullptr, nullptr,
        NT_S, KLIN_C, DH_C, 3 * DIM_C, DH_C, KLIN_C,
        (long)NT_S * 3 * DIM_C, DH_C,
        (long)HEADS_C * KLIN_C * DH_C, (long)KLIN_C * DH_C,
        (long)HEADS_C * NT_S * KLIN_C, (long)NT_S * KLIN_C,
        HEADS_C, 0.125f);
    // 13. softmax rows (len 128)
    softmax_rows<<<BS_C * HEADS_C * NT_S, 128>>>(SS, KLIN_C);
    // 14. O_S = S_S @ V_c   (65x64x128), head-merged (256,65,512)
    GEMM_SM<<<g3(DH_C, 64, NT_S, 64, BS_C * HEADS_C), 256>>>(
        SS, VC, OS, nullptr, nullptr,
        NT_S, DH_C, KLIN_C, KLIN_C, DH_C, DIM_C,
        (long)HEADS_C * NT_S * KLIN_C, (long)NT_S * KLIN_C,
        (long)HEADS_C * KLIN_C * DH_C, (long)KLIN_C * DH_C,
        (long)NT_S * DIM_C, DH_C,
        HEADS_C, 1.f);
    // 15. Y2 = O_S @ Wo_s + Z
    GEMM_BIG_R<<<g3(DIM_C, 128, MS, 128, 1), 256>>>(
        OS, Wo_s, Y2, nullptr, Z,
        MS, DIM_C, DIM_C, DIM_C, DIM_C, DIM_C,
        0, 0, 0, 0, 0, 0, 1, 1.f);
    // 16. H = gelu(Y2 @ W1 + b1)
    GEMM_BIG_G<<<g3(DFF_C, 128, MS, 128, 1), 256>>>(
        Y2, W1, H, b1, nullptr,
        MS, DFF_C, DIM_C, DIM_C, DFF_C, DFF_C,
        0, 0, 0, 0, 0, 0, 1, 1.f);
    // 17. out = H @ W2 + b2 + Y2
    GEMM_BIG_BR<<<g3(DIM_C, 128, MS, 128, 1), 256>>>(
        H, W2, out, b2, Y2,
        MS, DIM_C, DFF_C, DFF_C, DIM_C, DIM_C,
        0, 0, 0, 0, 0, 0, 1, 1.f);
    (void)in_sizes; (void)n_in; (void)out_size;
}

// round 2
// speedup vs baseline: 2.5031x; 2.5031x over previous
#include <cuda_runtime.h>
#include <math.h>

// ---------------------------------------------------------------------------
// TimeSformer block on sm_103a — round 1: all GEMMs on tensor cores via
// TF32 mma.sync.m16n8k8 (fp32 in/out, cvt.rna staging), double-buffered smem,
// fused epilogues; single-pass register softmax.
// ---------------------------------------------------------------------------

#define FRAMES_C  256
#define PATCHES_C 64
#define DIM_C     512
#define HEADS_C   8
#define DH_C      64
#define DFF_C     1024
#define KLIN_C    128
#define NT_T      257
#define NT_S      65
#define BT_C      64
#define BS_C      256

// ------------------------- scratch (device globals) ------------------------
__device__ float g_XT  [(size_t)BT_C * NT_T * DIM_C];
__device__ float g_QKVT[(size_t)BT_C * NT_T * 3 * DIM_C];
__device__ float g_ST  [(size_t)BT_C * HEADS_C * NT_T * NT_T];
__device__ float g_OT  [(size_t)BT_C * NT_T * DIM_C];
__device__ float g_Y1  [(size_t)BT_C * NT_T * DIM_C];
__device__ float g_Z   [(size_t)BS_C * NT_S * DIM_C];
__device__ float g_QKVS[(size_t)BS_C * NT_S * 3 * DIM_C];
__device__ float g_Et  [(size_t)KLIN_C * NT_S];
__device__ float g_KC  [(size_t)BS_C * HEADS_C * KLIN_C * DH_C];
__device__ float g_VC  [(size_t)BS_C * HEADS_C * KLIN_C * DH_C];
__device__ float g_SS  [(size_t)BS_C * HEADS_C * NT_S * KLIN_C];
__device__ float g_OS  [(size_t)BS_C * NT_S * DIM_C];
__device__ float g_Y2  [(size_t)BS_C * NT_S * DIM_C];
__device__ float g_H   [(size_t)BS_C * NT_S * DFF_C];

// ------------------------------- gathers -----------------------------------
__global__ void build_xt(const float* __restrict__ x) {
    long idx = (long)blockIdx.x * blockDim.x + threadIdx.x;
    const long total = (long)BT_C * NT_T * DIM_C;
    if (idx >= total) return;
    int d = (int)(idx % DIM_C);
    long r = idx / DIM_C;
    int t = (int)(r % NT_T);
    int p = (int)(r / NT_T);
    float v;
    if (t == 0) v = x[d];
    else        v = x[(long)(1 + (t - 1) * PATCHES_C + p) * DIM_C + d];
    g_XT[idx] = v;
}

__global__ void build_z() {
    long idx = (long)blockIdx.x * blockDim.x + threadIdx.x;
    const long total = (long)BS_C * NT_S * DIM_C;
    if (idx >= total) return;
    int d = (int)(idx % DIM_C);
    long r = idx / DIM_C;
    int s = (int)(r % NT_S);
    int f = (int)(r / NT_S);
    float v;
    if (s == 0) v = g_Y1[(long)(f & 63) * NT_T * DIM_C + d];
    else        v = g_Y1[(long)(s - 1) * NT_T * DIM_C + (long)(1 + f) * DIM_C + d];
    g_Z[idx] = v;
}

__global__ void transpose_E(const float* __restrict__ E) {
    int i = blockIdx.x * blockDim.x + threadIdx.x;
    if (i >= KLIN_C * NT_S) return;
    int j = i % NT_S, kc = i / NT_S;
    g_Et[i] = E[j * KLIN_C + kc];
}

// -------------------- single-pass register softmax --------------------------
template<int NC>
__global__ void softmax1(float* __restrict__ S) {
    constexpr int NTHR = 128;
    constexpr int PER = (NC + NTHR - 1) / NTHR;
    long row = blockIdx.x;
    float* p = S + row * (long)NC;
    int tid = threadIdx.x;
    int lane = tid & 31, warp = tid >> 5;
    __shared__ float red[4];

    float v[PER];
    float m = -1e30f;
    #pragma unroll
    for (int i = 0; i < PER; i++) {
        int c = tid + i * NTHR;
        v[i] = (c < NC) ? p[c] : -1e30f;
        m = fmaxf(m, v[i]);
    }
    #pragma unroll
    for (int s = 16; s > 0; s >>= 1) m = fmaxf(m, __shfl_xor_sync(0xffffffffu, m, s));
    if (lane == 0) red[warp] = m;
    __syncthreads();
    m = fmaxf(fmaxf(red[0], red[1]), fmaxf(red[2], red[3]));

    float sum = 0.f;
    #pragma unroll
    for (int i = 0; i < PER; i++) {
        v[i] = __expf(v[i] - m) ;
        int c = tid + i * NTHR;
        if (c < NC) sum += v[i];
    }
    #pragma unroll
    for (int s = 16; s > 0; s >>= 1) sum += __shfl_xor_sync(0xffffffffu, sum, s);
    __syncthreads();
    if (lane == 0) red[warp] = sum;
    __syncthreads();
    float inv = 1.f / (red[0] + red[1] + red[2] + red[3]);
    #pragma unroll
    for (int i = 0; i < PER; i++) {
        int c = tid + i * NTHR;
        if (c < NC) p[c] = v[i] * inv;
    }
}

// ----------------------------- mma helpers ----------------------------------
__device__ __forceinline__ unsigned f2tf(float f) {
    unsigned u;
    asm("cvt.rna.tf32.f32 %0, %1;" : "=r"(u) : "f"(f));
    return u;
}

__device__ __forceinline__ void mma_tf32(float c[4], const unsigned a[4], const unsigned b[2]) {
    asm volatile(
        "mma.sync.aligned.m16n8k8.row.col.f32.tf32.tf32.f32 "
        "{%0,%1,%2,%3},{%4,%5,%6,%7},{%8,%9},{%0,%1,%2,%3};\n"
        : "+f"(c[0]), "+f"(c[1]), "+f"(c[2]), "+f"(c[3])
        : "r"(a[0]), "r"(a[1]), "r"(a[2]), "r"(a[3]), "r"(b[0]), "r"(b[1]));
}

// ------------------- TF32 tensor-core strided-batched GEMM ------------------
// C[e] = alpha * A[e] @ op(B[e]) (+epilogue). TRB: B is (N x K) row-major.
// EPI: 0 none | 1 bias+exact-gelu | 2 bias+residual | 3 residual
// VEC: float4 staging; requires K%16==0 and N%BN==0 for the B tile.
template<int BM, int BN, int WROWS, int WCOLS, bool TRB, int EPI, bool VEC>
__global__ void __launch_bounds__(WROWS * WCOLS * 32)
mma_gemm(const float* __restrict__ A, const float* __restrict__ B,
         float* __restrict__ C, const float* __restrict__ bias,
         const float* __restrict__ R,
         int M, int N, int K, int lda, int ldb, int ldc,
         long soA, long siA, long soB, long siB, long soC, long siC,
         int NI, float alpha)
{
    constexpr int BK = 16;
    constexpr int NWARP = WROWS * WCOLS;
    constexpr int NTH = NWARP * 32;
    constexpr int WM = BM / WROWS, WN = BN / WCOLS;
    constexpr int MT = WM / 16, NT = WN / 8;
    constexpr int PAD = 4;
    constexpr int AV4 = (BM * BK) / (4 * NTH) > 0 ? (BM * BK) / (4 * NTH) : 1;
    constexpr int BV4 = (BN * BK) / (4 * NTH) > 0 ? (BN * BK) / (4 * NTH) : 1;
    constexpr int ASC = (BM * BK) / NTH;
    constexpr int BSC = (BN * BK) / NTH;

    __shared__ unsigned As[2][BK][BM + PAD];
    __shared__ unsigned Bs[2][BK][BN + PAD];

    int e = blockIdx.z;
    int o = e / NI, ii = e - o * NI;
    A += o * soA + (long)ii * siA;
    B += o * soB + (long)ii * siB;
    C += o * soC + (long)ii * siC;
    const float* Rp = R ? (R + o * soC + (long)ii * siC) : (const float*)0;

    const int bm = blockIdx.y * BM, bn = blockIdx.x * BN;
    const int tid = threadIdx.x, lane = tid & 31, warp = tid >> 5;
    const int wr = warp / WCOLS, wc = warp % WCOLS;

    float c[MT][NT][4];
    #pragma unroll
    for (int i = 0; i < MT; i++)
        #pragma unroll
        for (int j = 0; j < NT; j++)
            #pragma unroll
            for (int q = 0; q < 4; q++) c[i][j][q] = 0.f;

    float4 a4[AV4], b4[BV4];
    float aS[ASC], bS[BSC];

    auto loadg = [&](int t) {
        int k0 = t * BK;
        if constexpr (VEC) {
            #pragma unroll
            for (int i = 0; i < AV4; i++) {
                int s = tid + i * NTH;
                int row = s / (BK / 4), seg = s % (BK / 4);
                int gr = bm + row;
                a4[i] = (gr < M) ? *(const float4*)(A + (long)gr * lda + k0 + seg * 4)
                                 : make_float4(0.f, 0.f, 0.f, 0.f);
            }
            #pragma unroll
            for (int i = 0; i < BV4; i++) {
                if constexpr (!TRB) {
                    int s = tid + i * NTH;
                    int kk = s / (BN / 4), seg = s % (BN / 4);
                    b4[i] = *(const float4*)(B + (long)(k0 + kk) * ldb + bn + seg * 4);
                } else {
                    int s = tid + i * NTH;
                    int n = s / (BK / 4), seg = s % (BK / 4);
                    int gc = bn + n;
                    b4[i] = (gc < N) ? *(const float4*)(B + (long)gc * ldb + k0 + seg * 4)
                                     : make_float4(0.f, 0.f, 0.f, 0.f);
                }
            }
        } else {
            #pragma unroll
            for (int i = 0; i < ASC; i++) {
                int s = tid + i * NTH;
                int row = s / BK, kk = s % BK;
                int gr = bm + row, gk = k0 + kk;
                aS[i] = (gr < M && gk < K) ? A[(long)gr * lda + gk] : 0.f;
            }
            #pragma unroll
            for (int i = 0; i < BSC; i++) {
                int s = tid + i * NTH;
                if constexpr (!TRB) {
                    int kk = s / BN, n = s % BN;
                    int gk = k0 + kk, gc = bn + n;
                    bS[i] = (gk < K && gc < N) ? B[(long)gk * ldb + gc] : 0.f;
                } else {
                    int n = s / BK, kk = s % BK;
                    int gc = bn + n, gk = k0 + kk;
                    bS[i] = (gc < N && gk < K) ? B[(long)gc * ldb + gk] : 0.f;
                }
            }
        }
    };

    auto stores = [&](int buf) {
        if constexpr (VEC) {
            #pragma unroll
            for (int i = 0; i < AV4; i++) {
                int s = tid + i * NTH;
                int row = s / (BK / 4), seg = s % (BK / 4);
                const float* ap = (const float*)&a4[i];
                #pragma unroll
                for (int j = 0; j < 4; j++) As[buf][seg * 4 + j][row] = f2tf(ap[j]);
            }
            #pragma unroll
            for (int i = 0; i < BV4; i++) {
                const float* bp = (const float*)&b4[i];
                if constexpr (!TRB) {
                    int s = tid + i * NTH;
                    int kk = s / (BN / 4), seg = s % (BN / 4);
                    #pragma unroll
                    for (int j = 0; j < 4; j++) Bs[buf][kk][seg * 4 + j] = f2tf(bp[j]);
                } else {
                    int s = tid + i * NTH;
                    int n = s / (BK / 4), seg = s % (BK / 4);
                    #pragma unroll
                    for (int j = 0; j < 4; j++) Bs[buf][seg * 4 + j][n] = f2tf(bp[j]);
                }
            }
        } else {
            #pragma unroll
            for (int i = 0; i < ASC; i++) {
                int s = tid + i * NTH;
                int row = s / BK, kk = s % BK;
                As[buf][kk][row] = f2tf(aS[i]);
            }
            #pragma unroll
            for (int i = 0; i < BSC; i++) {
                int s = tid + i * NTH;
                if constexpr (!TRB) {
                    int kk = s / BN, n = s % BN;
                    Bs[buf][kk][n] = f2tf(bS[i]);
                } else {
                    int n = s / BK, kk = s % BK;
                    Bs[buf][kk][n] = f2tf(bS[i]);
                }
            }
        }
    };

    auto comp = [&](int cu) {
        #pragma unroll
        for (int ks = 0; ks < BK / 8; ks++) {
            int kb = ks * 8;
            unsigned af[MT][4], bf[NT][2];
            #pragma unroll
            for (int mt = 0; mt < MT; mt++) {
                int r0 = wr * WM + mt * 16 + (lane >> 2);
                int kc = kb + (lane & 3);
                af[mt][0] = As[cu][kc][r0];
                af[mt][1] = As[cu][kc][r0 + 8];
                af[mt][2] = As[cu][kc + 4][r0];
                af[mt][3] = As[cu][kc + 4][r0 + 8];
            }
            #pragma unroll
            for (int nt = 0; nt < NT; nt++) {
                int c0 = wc * WN + nt * 8 + (lane >> 2);
                int kc = kb + (lane & 3);
                bf[nt][0] = Bs[cu][kc][c0];
                bf[nt][1] = Bs[cu][kc + 4][c0];
            }
            #pragma unroll
            for (int mt = 0; mt < MT; mt++)
                #pragma unroll
                for (int nt = 0; nt < NT; nt++)
                    mma_tf32(c[mt][nt], af[mt], bf[nt]);
        }
    };

    int ntl = (K + BK - 1) / BK;
    loadg(0);
    stores(0);
    __syncthreads();
    int cu = 0;
    for (int t = 0; t < ntl; t++) {
        if (t + 1 < ntl) loadg(t + 1);
        comp(cu);
        if (t + 1 < ntl) stores(cu ^ 1);
        __syncthreads();
        cu ^= 1;
    }

    // epilogue
    #pragma unroll
    for (int mt = 0; mt < MT; mt++) {
        #pragma unroll
        for (int nt = 0; nt < NT; nt++) {
            int row0 = bm + wr * WM + mt * 16 + (lane >> 2);
            int col0 = bn + wc * WN + nt * 8 + (lane & 3) * 2;
            #pragma unroll
            for (int h = 0; h < 2; h++) {
                int r = row0 + h * 8;
                if (r >= M) continue;
                #pragma unroll
                for (int j = 0; j < 2; j++) {
                    int gc = col0 + j;
                    if (gc >= N) continue;
                    float v = c[mt][nt][h * 2 + j] * alpha;
                    if constexpr (EPI == 1) {
                        v += bias[gc];
                        v = 0.5f * v * (1.f + erff(v * 0.70710678118654752f));
                    } else if constexpr (EPI == 2) {
                        v += bias[gc] + Rp[(long)r * ldc + gc];
                    } else if constexpr (EPI == 3) {
                        v += Rp[(long)r * ldc + gc];
                    }
                    C[(long)r * ldc + gc] = v;
                }
            }
        }
    }
}

// instantiation aliases
#define BIG0  mma_gemm<128,128,2,4,false,0,true>
#define BIGG  mma_gemm<128,128,2,4,false,1,true>
#define BIGBR mma_gemm<128,128,2,4,false,2,true>
#define BIGR  mma_gemm<128,128,2,4,false,3,true>
#define SMN   mma_gemm<64,64,2,2,false,0,false>
#define SMT   mma_gemm<64,64,2,2,true,0,false>

static inline dim3 g3(int N, int BN, int M, int BM, int Z) {
    return dim3((N + BN - 1) / BN, (M + BM - 1) / BM, Z);
}

extern "C" void kernel_launch(void* const* d_in, const int* in_sizes, int n_in,
                              void* d_out, int out_size) {
    const float* x      = (const float*)d_in[0];
    const float* Wqkv_t = (const float*)d_in[1];
    const float* Wo_t   = (const float*)d_in[2];
    const float* Wqkv_s = (const float*)d_in[3];
    const float* Wo_s   = (const float*)d_in[4];
    const float* E      = (const float*)d_in[5];
    const float* W1     = (const float*)d_in[6];
    const float* b1     = (const float*)d_in[7];
    const float* W2     = (const float*)d_in[8];
    const float* b2     = (const float*)d_in[9];
    float* out = (float*)d_out;

    float *XT, *QKVT, *ST, *OT, *Y1, *Z, *QKVS, *Et, *KC, *VC, *SS, *OS, *Y2, *H;
    cudaGetSymbolAddress((void**)&XT,   g_XT);
    cudaGetSymbolAddress((void**)&QKVT, g_QKVT);
    cudaGetSymbolAddress((void**)&ST,   g_ST);
    cudaGetSymbolAddress((void**)&OT,   g_OT);
    cudaGetSymbolAddress((void**)&Y1,   g_Y1);
    cudaGetSymbolAddress((void**)&Z,    g_Z);
    cudaGetSymbolAddress((void**)&QKVS, g_QKVS);
    cudaGetSymbolAddress((void**)&Et,   g_Et);
    cudaGetSymbolAddress((void**)&KC,   g_KC);
    cudaGetSymbolAddress((void**)&VC,   g_VC);
    cudaGetSymbolAddress((void**)&SS,   g_SS);
    cudaGetSymbolAddress((void**)&OS,   g_OS);
    cudaGetSymbolAddress((void**)&Y2,   g_Y2);
    cudaGetSymbolAddress((void**)&H,    g_H);

    const int MT = BT_C * NT_T;   // 16448
    const int MS = BS_C * NT_S;   // 16640

    // 1. gather -> XT
    {
        long total = (long)BT_C * NT_T * DIM_C;
        build_xt<<<(unsigned)((total + 255) / 256), 256>>>(x);
    }
    // 2. QKV_T = XT @ Wqkv_t
    BIG0<<<g3(3 * DIM_C, 128, MT, 128, 1), 256>>>(
        XT, Wqkv_t, QKVT, nullptr, nullptr,
        MT, 3 * DIM_C, DIM_C, DIM_C, 3 * DIM_C, 3 * DIM_C,
        0, 0, 0, 0, 0, 0, 1, 1.f);
    // 3. S_T = 0.125 * Q @ K^T (512 batched 257x257x64)
    SMT<<<g3(NT_T, 64, NT_T, 64, BT_C * HEADS_C), 128>>>(
        QKVT, QKVT + DIM_C, ST, nullptr, nullptr,
        NT_T, NT_T, DH_C, 3 * DIM_C, 3 * DIM_C, NT_T,
        (long)NT_T * 3 * DIM_C, DH_C, (long)NT_T * 3 * DIM_C, DH_C,
        (long)HEADS_C * NT_T * NT_T, (long)NT_T * NT_T,
        HEADS_C, 0.125f);
    // 4. softmax
    softmax1<NT_T><<<BT_C * HEADS_C * NT_T, 128>>>(ST);
    // 5. O_T = S @ V (257x64x257)
    SMN<<<g3(DH_C, 64, NT_T, 64, BT_C * HEADS_C), 128>>>(
        ST, QKVT + 2 * DIM_C, OT, nullptr, nullptr,
        NT_T, DH_C, NT_T, NT_T, 3 * DIM_C, DIM_C,
        (long)HEADS_C * NT_T * NT_T, (long)NT_T * NT_T,
        (long)NT_T * 3 * DIM_C, DH_C,
        (long)NT_T * DIM_C, DH_C,
        HEADS_C, 1.f);
    // 6. Y1 = O_T @ Wo_t + XT
    BIGR<<<g3(DIM_C, 128, MT, 128, 1), 256>>>(
        OT, Wo_t, Y1, nullptr, XT,
        MT, DIM_C, DIM_C, DIM_C, DIM_C, DIM_C,
        0, 0, 0, 0, 0, 0, 1, 1.f);
    // 7. gather -> Z
    {
        long total = (long)BS_C * NT_S * DIM_C;
        build_z<<<(unsigned)((total + 255) / 256), 256>>>();
    }
    // 8. QKV_S = Z @ Wqkv_s
    BIG0<<<g3(3 * DIM_C, 128, MS, 128, 1), 256>>>(
        Z, Wqkv_s, QKVS, nullptr, nullptr,
        MS, 3 * DIM_C, DIM_C, DIM_C, 3 * DIM_C, 3 * DIM_C,
        0, 0, 0, 0, 0, 0, 1, 1.f);
    // 9. E^T
    transpose_E<<<(KLIN_C * NT_S + 255) / 256, 256>>>(E);
    // 10/11. K_c, V_c = E^T @ {K,V}  (2048 batched 128x64x65)
    SMN<<<g3(DH_C, 64, KLIN_C, 64, BS_C * HEADS_C), 128>>>(
        Et, QKVS + DIM_C, KC, nullptr, nullptr,
        KLIN_C, DH_C, NT_S, NT_S, 3 * DIM_C, DH_C,
        0, 0, (long)NT_S * 3 * DIM_C, DH_C,
        (long)HEADS_C * KLIN_C * DH_C, (long)KLIN_C * DH_C,
        HEADS_C, 1.f);
    SMN<<<g3(DH_C, 64, KLIN_C, 64, BS_C * HEADS_C), 128>>>(
        Et, QKVS + 2 * DIM_C, VC, nullptr, nullptr,
        KLIN_C, DH_C, NT_S, NT_S, 3 * DIM_C, DH_C,
        0, 0, (long)NT_S * 3 * DIM_C, DH_C,
        (long)HEADS_C * KLIN_C * DH_C, (long)KLIN_C * DH_C,
        HEADS_C, 1.f);
    // 12. S_S = 0.125 * Q @ K_c^T (2048 batched 65x128x64)
    SMT<<<g3(KLIN_C, 64, NT_S, 64, BS_C * HEADS_C), 128>>>(
        QKVS, KC, SS, nullptr, nullptr,
        NT_S, KLIN_C, DH_C, 3 * DIM_C, DH_C, KLIN_C,
        (long)NT_S * 3 * DIM_C, DH_C,
        (long)HEADS_C * KLIN_C * DH_C, (long)KLIN_C * DH_C,
        (long)HEADS_C * NT_S * KLIN_C, (long)NT_S * KLIN_C,
        HEADS_C, 0.125f);
    // 13. softmax (128 cols)
    softmax1<KLIN_C><<<BS_C * HEADS_C * NT_S, 128>>>(SS);
    // 14. O_S = S_S @ V_c (65x64x128)
    SMN<<<g3(DH_C, 64, NT_S, 64, BS_C * HEADS_C), 128>>>(
        SS, VC, OS, nullptr, nullptr,
        NT_S, DH_C, KLIN_C, KLIN_C, DH_C, DIM_C,
        (long)HEADS_C * NT_S * KLIN_C, (long)NT_S * KLIN_C,
        (long)HEADS_C * KLIN_C * DH_C, (long)KLIN_C * DH_C,
        (long)NT_S * DIM_C, DH_C,
        HEADS_C, 1.f);
    // 15. Y2 = O_S @ Wo_s + Z
    BIGR<<<g3(DIM_C, 128, MS, 128, 1), 256>>>(
        OS, Wo_s, Y2, nullptr, Z,
        MS, DIM_C, DIM_C, DIM_C, DIM_C, DIM_C,
        0, 0, 0, 0, 0, 0, 1, 1.f);
    // 16. H = gelu(Y2 @ W1 + b1)
    BIGG<<<g3(DFF_C, 128, MS, 128, 1), 256>>>(
        Y2, W1, H, b1, nullptr,
        MS, DFF_C, DIM_C, DIM_C, DFF_C, DFF_C,
        0, 0, 0, 0, 0, 0, 1, 1.f);
    // 17. out = H @ W2 + b2 + Y2
    BIGBR<<<g3(DIM_C, 128, MS, 128, 1), 256>>>(
        H, W2, out, b2, Y2,
        MS, DIM_C, DFF_C, DFF_C, DIM_C, DIM_C,
        0, 0, 0, 0, 0, 0, 1, 1.f);
    (void)in_sizes; (void)n_in; (void)out_size;
}

// round 3
// speedup vs baseline: 2.7301x; 1.0907x over previous
#include <cuda_runtime.h>
#include <math.h>

// ---------------------------------------------------------------------------
// TimeSformer block on sm_103a — round 2: TF32 mma everywhere, inputs
// pre-rounded to tf32 (no cvt in GEMM hot loops), all staging vectorized
// (float4) via K/lda padding with zero-initialized pad regions.
// ---------------------------------------------------------------------------

#define FRAMES_C  256
#define PATCHES_C 64
#define DIM_C     512
#define HEADS_C   8
#define DH_C      64
#define DFF_C     1024
#define KLIN_C    128
#define NT_T      257
#define NT_S      65
#define BT_C      64
#define BS_C      256
#define STLD      272          // padded row stride / K for O_T  (257 -> 272)
#define ETLD      80           // padded row stride / K for KC,VC (65 -> 80)

// ------------------------- scratch (device globals) ------------------------
// NOTE: device globals are zero-initialized at module load; pad regions are
// never written by any kernel, so they stay exactly 0.0f across graph replays.
__device__ float g_XT  [(size_t)BT_C * NT_T * DIM_C];
__device__ float g_QKVT[((size_t)BT_C * NT_T + 16) * 3 * DIM_C];     // +16 pad rows
__device__ float g_ST  [(size_t)BT_C * HEADS_C * NT_T * STLD];
__device__ float g_OT  [(size_t)BT_C * NT_T * DIM_C];
__device__ float g_Y1  [(size_t)BT_C * NT_T * DIM_C];
__device__ float g_Z   [(size_t)BS_C * NT_S * DIM_C];
__device__ float g_QKVS[((size_t)BS_C * NT_S + 16) * 3 * DIM_C];     // +16 pad rows
__device__ float g_Et  [(size_t)KLIN_C * ETLD];
__device__ float g_KC  [(size_t)BS_C * HEADS_C * KLIN_C * DH_C];
__device__ float g_VC  [(size_t)BS_C * HEADS_C * KLIN_C * DH_C];
__device__ float g_SS  [(size_t)BS_C * HEADS_C * NT_S * KLIN_C];
__device__ float g_OS  [(size_t)BS_C * NT_S * DIM_C];
__device__ float g_Y2  [(size_t)BS_C * NT_S * DIM_C];
__device__ float g_H   [(size_t)BS_C * NT_S * DFF_C];
// rounded weight copies
__device__ float g_Wqkv_t[(size_t)DIM_C * 3 * DIM_C];
__device__ float g_Wo_t  [(size_t)DIM_C * DIM_C];
__device__ float g_Wqkv_s[(size_t)DIM_C * 3 * DIM_C];
__device__ float g_Wo_s  [(size_t)DIM_C * DIM_C];
__device__ float g_W1    [(size_t)DIM_C * DFF_C];
__device__ float g_W2    [(size_t)DFF_C * DIM_C];

__device__ __forceinline__ float f2tf(float f) {
    unsigned u;
    asm("cvt.rna.tf32.f32 %0, %1;" : "=r"(u) : "f"(f));
    return __uint_as_float(u);
}

// ------------------------------- prep kernels -------------------------------
__global__ void round_copy(float* __restrict__ dst, const float* __restrict__ src, int n) {
    int i = blockIdx.x * blockDim.x + threadIdx.x;
    if (i < n) dst[i] = f2tf(src[i]);
}

__global__ void build_xt(const float* __restrict__ x) {
    long idx = (long)blockIdx.x * blockDim.x + threadIdx.x;
    const long total = (long)BT_C * NT_T * DIM_C;
    if (idx >= total) return;
    int d = (int)(idx % DIM_C);
    long r = idx / DIM_C;
    int t = (int)(r % NT_T);
    int p = (int)(r / NT_T);
    float v;
    if (t == 0) v = x[d];
    else        v = x[(long)(1 + (t - 1) * PATCHES_C + p) * DIM_C + d];
    g_XT[idx] = f2tf(v);
}

__global__ void build_z() {
    long idx = (long)blockIdx.x * blockDim.x + threadIdx.x;
    const long total = (long)BS_C * NT_S * DIM_C;
    if (idx >= total) return;
    int d = (int)(idx % DIM_C);
    long r = idx / DIM_C;
    int s = (int)(r % NT_S);
    int f = (int)(r / NT_S);
    float v;
    if (s == 0) v = g_Y1[(long)(f & 63) * NT_T * DIM_C + d];
    else        v = g_Y1[(long)(s - 1) * NT_T * DIM_C + (long)(1 + f) * DIM_C + d];
    g_Z[idx] = v;   // Y1 already tf32-rounded by its epilogue
}

__global__ void transpose_E(const float* __restrict__ E) {
    int i = blockIdx.x * blockDim.x + threadIdx.x;
    if (i >= KLIN_C * NT_S) return;
    int j = i % NT_S, kc = i / NT_S;
    g_Et[kc * ETLD + j] = f2tf(E[j * KLIN_C + kc]);   // pad cols [65,80) stay 0
}

// -------------------- single-pass register softmax --------------------------
template<int NC, int LD>
__global__ void softmax1(float* __restrict__ S) {
    constexpr int NTHR = 128;
    constexpr int PER = (NC + NTHR - 1) / NTHR;
    long row = blockIdx.x;
    float* p = S + row * (long)LD;
    int tid = threadIdx.x;
    int lane = tid & 31, warp = tid >> 5;
    __shared__ float red[4];

    float v[PER];
    float m = -1e30f;
    #pragma unroll
    for (int i = 0; i < PER; i++) {
        int c = tid + i * NTHR;
        v[i] = (c < NC) ? p[c] : -1e30f;
        m = fmaxf(m, v[i]);
    }
    #pragma unroll
    for (int s = 16; s > 0; s >>= 1) m = fmaxf(m, __shfl_xor_sync(0xffffffffu, m, s));
    if (lane == 0) red[warp] = m;
    __syncthreads();
    m = fmaxf(fmaxf(red[0], red[1]), fmaxf(red[2], red[3]));

    float sum = 0.f;
    #pragma unroll
    for (int i = 0; i < PER; i++) {
        v[i] = __expf(v[i] - m);
        int c = tid + i * NTHR;
        if (c < NC) sum += v[i];
    }
    #pragma unroll
    for (int s = 16; s > 0; s >>= 1) sum += __shfl_xor_sync(0xffffffffu, sum, s);
    __syncthreads();
    if (lane == 0) red[warp] = sum;
    __syncthreads();
    float inv = 1.f / (red[0] + red[1] + red[2] + red[3]);
    #pragma unroll
    for (int i = 0; i < PER; i++) {
        int c = tid + i * NTHR;
        if (c < NC) p[c] = f2tf(v[i] * inv);
    }
}

// ----------------------------- mma helper -----------------------------------
__device__ __forceinline__ void mma_tf32(float c[4], const unsigned a[4], const unsigned b[2]) {
    asm volatile(
        "mma.sync.aligned.m16n8k8.row.col.f32.tf32.tf32.f32 "
        "{%0,%1,%2,%3},{%4,%5,%6,%7},{%8,%9},{%0,%1,%2,%3};\n"
        : "+f"(c[0]), "+f"(c[1]), "+f"(c[2]), "+f"(c[3])
        : "r"(a[0]), "r"(a[1]), "r"(a[2]), "r"(a[3]), "r"(b[0]), "r"(b[1]));
}

// ------------------- TF32 tensor-core strided-batched GEMM ------------------
// All inputs are already tf32-rounded fp32 bit patterns.
// Requirements (guaranteed by caller): K % 16 == 0, lda/ldb % 4 == 0,
// all float4 loads in-bounds (via padded buffers); row guards only.
// TRB: B is (N x K) row-major. EPI: 0 none | 1 bias+gelu | 2 bias+res | 3 res.
template<int BM, int BN, int WROWS, int WCOLS, bool TRB, int EPI, bool ROUND>
__global__ void __launch_bounds__(WROWS * WCOLS * 32)
mma_gemm(const float* __restrict__ A, const float* __restrict__ B,
         float* __restrict__ C, const float* __restrict__ bias,
         const float* __restrict__ R,
         int M, int N, int K, int lda, int ldb, int ldc,
         long soA, long siA, long soB, long siB, long soC, long siC,
         int NI, float alpha)
{
    constexpr int BK = 16;
    constexpr int NWARP = WROWS * WCOLS;
    constexpr int NTH = NWARP * 32;
    constexpr int WM = BM / WROWS, WN = BN / WCOLS;
    constexpr int MT = WM / 16, NT = WN / 8;
    constexpr int PAD = 4;
    constexpr int AV4 = (BM * BK) / (4 * NTH);
    constexpr int BV4 = (BN * BK) / (4 * NTH);

    __shared__ float As[2][BK][BM + PAD];
    __shared__ float Bs[2][BK][BN + PAD];

    int e = blockIdx.z;
    int o = e / NI, ii = e - o * NI;
    A += o * soA + (long)ii * siA;
    B += o * soB + (long)ii * siB;
    C += o * soC + (long)ii * siC;
    const float* Rp = R ? (R + o * soC + (long)ii * siC) : (const float*)0;

    const int bm = blockIdx.y * BM, bn = blockIdx.x * BN;
    const int tid = threadIdx.x, lane = tid & 31, warp = tid >> 5;
    const int wr = warp / WCOLS, wc = warp % WCOLS;

    float c[MT][NT][4];
    #pragma unroll
    for (int i = 0; i < MT; i++)
        #pragma unroll
        for (int j = 0; j < NT; j++)
            #pragma unroll
            for (int q = 0; q < 4; q++) c[i][j][q] = 0.f;

    float4 a4[AV4], b4[BV4];

    auto loadg = [&](int t) {
        int k0 = t * BK;
        #pragma unroll
        for (int i = 0; i < AV4; i++) {
            int s = tid + i * NTH;
            int row = s / (BK / 4), seg = s % (BK / 4);
            int gr = bm + row;
            a4[i] = (gr < M) ? *(const float4*)(A + (long)gr * lda + k0 + seg * 4)
                             : make_float4(0.f, 0.f, 0.f, 0.f);
        }
        #pragma unroll
        for (int i = 0; i < BV4; i++) {
            int s = tid + i * NTH;
            if constexpr (!TRB) {
                int kk = s / (BN / 4), seg = s % (BN / 4);
                b4[i] = *(const float4*)(B + (long)(k0 + kk) * ldb + bn + seg * 4);
            } else {
                int n = s / (BK / 4), seg = s % (BK / 4);
                int gc = bn + n;
                b4[i] = (gc < N) ? *(const float4*)(B + (long)gc * ldb + k0 + seg * 4)
                                 : make_float4(0.f, 0.f, 0.f, 0.f);
            }
        }
    };

    auto stores = [&](int buf) {
        #pragma unroll
        for (int i = 0; i < AV4; i++) {
            int s = tid + i * NTH;
            int row = s / (BK / 4), seg = s % (BK / 4);
            const float* ap = (const float*)&a4[i];
            #pragma unroll
            for (int j = 0; j < 4; j++) As[buf][seg * 4 + j][row] = ap[j];
        }
        #pragma unroll
        for (int i = 0; i < BV4; i++) {
            const float* bp = (const float*)&b4[i];
            int s = tid + i * NTH;
            if constexpr (!TRB) {
                int kk = s / (BN / 4), seg = s % (BN / 4);
                #pragma unroll
                for (int j = 0; j < 4; j++) Bs[buf][kk][seg * 4 + j] = bp[j];
            } else {
                int n = s / (BK / 4), seg = s % (BK / 4);
                #pragma unroll
                for (int j = 0; j < 4; j++) Bs[buf][seg * 4 + j][n] = bp[j];
            }
        }
    };

    auto comp = [&](int cu) {
        #pragma unroll
        for (int ks = 0; ks < BK / 8; ks++) {
            int kb = ks * 8;
            unsigned af[MT][4], bf[NT][2];
            #pragma unroll
            for (int mt = 0; mt < MT; mt++) {
                int r0 = wr * WM + mt * 16 + (lane >> 2);
                int kc = kb + (lane & 3);
                af[mt][0] = __float_as_uint(As[cu][kc][r0]);
                af[mt][1] = __float_as_uint(As[cu][kc][r0 + 8]);
                af[mt][2] = __float_as_uint(As[cu][kc + 4][r0]);
                af[mt][3] = __float_as_uint(As[cu][kc + 4][r0 + 8]);
            }
            #pragma unroll
            for (int nt = 0; nt < NT; nt++) {
                int c0 = wc * WN + nt * 8 + (lane >> 2);
                int kc = kb + (lane & 3);
                bf[nt][0] = __float_as_uint(Bs[cu][kc][c0]);
                bf[nt][1] = __float_as_uint(Bs[cu][kc + 4][c0]);
            }
            #pragma unroll
            for (int mt = 0; mt < MT; mt++)
                #pragma unroll
                for (int nt = 0; nt < NT; nt++)
                    mma_tf32(c[mt][nt], af[mt], bf[nt]);
        }
    };

    int ntl = K / BK;
    loadg(0);
    stores(0);
    __syncthreads();
    int cu = 0;
    for (int t = 0; t < ntl; t++) {
        if (t + 1 < ntl) loadg(t + 1);
        comp(cu);
        if (t + 1 < ntl) stores(cu ^ 1);
        __syncthreads();
        cu ^= 1;
    }

    #pragma unroll
    for (int mt = 0; mt < MT; mt++) {
        #pragma unroll
        for (int nt = 0; nt < NT; nt++) {
            int row0 = bm + wr * WM + mt * 16 + (lane >> 2);
            int col0 = bn + wc * WN + nt * 8 + (lane & 3) * 2;
            #pragma unroll
            for (int h = 0; h < 2; h++) {
                int r = row0 + h * 8;
                if (r >= M) continue;
                #pragma unroll
                for (int j = 0; j < 2; j++) {
                    int gc = col0 + j;
                    if (gc >= N) continue;
                    float v = c[mt][nt][h * 2 + j] * alpha;
                    if constexpr (EPI == 1) {
                        v += bias[gc];
                        v = 0.5f * v * (1.f + erff(v * 0.70710678118654752f));
                    } else if constexpr (EPI == 2) {
                        v += bias[gc] + Rp[(long)r * ldc + gc];
                    } else if constexpr (EPI == 3) {
                        v += Rp[(long)r * ldc + gc];
                    }
                    if constexpr (ROUND) v = f2tf(v);
                    C[(long)r * ldc + gc] = v;
                }
            }
        }
    }
}

// instantiation aliases
#define BIG0  mma_gemm<128,128,2,4,false,0,true>
#define BIGG  mma_gemm<128,128,2,4,false,1,true>
#define BIGBR mma_gemm<128,128,2,4,false,2,false>
#define BIGR  mma_gemm<128,128,2,4,false,3,true>
#define SMN   mma_gemm<64,64,2,2,false,0,true>
#define SMNS  mma_gemm<64,64,2,2,false,0,false>
#define SMT   mma_gemm<64,64,2,2,true,0,false>

static inline dim3 g3(int N, int BN, int M, int BM, int Z) {
    return dim3((N + BN - 1) / BN, (M + BM - 1) / BM, Z);
}

extern "C" void kernel_launch(void* const* d_in, const int* in_sizes, int n_in,
                              void* d_out, int out_size) {
    const float* x      = (const float*)d_in[0];
    const float* Wqkv_t = (const float*)d_in[1];
    const float* Wo_t   = (const float*)d_in[2];
    const float* Wqkv_s = (const float*)d_in[3];
    const float* Wo_s   = (const float*)d_in[4];
    const float* E      = (const float*)d_in[5];
    const float* W1     = (const float*)d_in[6];
    const float* b1     = (const float*)d_in[7];
    const float* W2     = (const float*)d_in[8];
    const float* b2     = (const float*)d_in[9];
    float* out = (float*)d_out;

    float *XT, *QKVT, *ST, *OT, *Y1, *Z, *QKVS, *Et, *KC, *VC, *SS, *OS, *Y2, *H;
    float *rWqkv_t, *rWo_t, *rWqkv_s, *rWo_s, *rW1, *rW2;
    cudaGetSymbolAddress((void**)&XT,   g_XT);
    cudaGetSymbolAddress((void**)&QKVT, g_QKVT);
    cudaGetSymbolAddress((void**)&ST,   g_ST);
    cudaGetSymbolAddress((void**)&OT,   g_OT);
    cudaGetSymbolAddress((void**)&Y1,   g_Y1);
    cudaGetSymbolAddress((void**)&Z,    g_Z);
    cudaGetSymbolAddress((void**)&QKVS, g_QKVS);
    cudaGetSymbolAddress((void**)&Et,   g_Et);
    cudaGetSymbolAddress((void**)&KC,   g_KC);
    cudaGetSymbolAddress((void**)&VC,   g_VC);
    cudaGetSymbolAddress((void**)&SS,   g_SS);
    cudaGetSymbolAddress((void**)&OS,   g_OS);
    cudaGetSymbolAddress((void**)&Y2,   g_Y2);
    cudaGetSymbolAddress((void**)&H,    g_H);
    cudaGetSymbolAddress((void**)&rWqkv_t, g_Wqkv_t);
    cudaGetSymbolAddress((void**)&rWo_t,   g_Wo_t);
    cudaGetSymbolAddress((void**)&rWqkv_s, g_Wqkv_s);
    cudaGetSymbolAddress((void**)&rWo_s,   g_Wo_s);
    cudaGetSymbolAddress((void**)&rW1,     g_W1);
    cudaGetSymbolAddress((void**)&rW2,     g_W2);

    const int MT = BT_C * NT_T;   // 16448
    const int MS = BS_C * NT_S;   // 16640

    // 0. round weights to tf32
    round_copy<<<(DIM_C * 3 * DIM_C + 255) / 256, 256>>>(rWqkv_t, Wqkv_t, DIM_C * 3 * DIM_C);
    round_copy<<<(DIM_C * DIM_C + 255) / 256, 256>>>(rWo_t, Wo_t, DIM_C * DIM_C);
    round_copy<<<(DIM_C * 3 * DIM_C + 255) / 256, 256>>>(rWqkv_s, Wqkv_s, DIM_C * 3 * DIM_C);
    round_copy<<<(DIM_C * DIM_C + 255) / 256, 256>>>(rWo_s, Wo_s, DIM_C * DIM_C);
    round_copy<<<(DIM_C * DFF_C + 255) / 256, 256>>>(rW1, W1, DIM_C * DFF_C);
    round_copy<<<(DFF_C * DIM_C + 255) / 256, 256>>>(rW2, W2, DFF_C * DIM_C);
    transpose_E<<<(KLIN_C * NT_S + 255) / 256, 256>>>(E);

    // 1. gather -> XT (rounded)
    {
        long total = (long)BT_C * NT_T * DIM_C;
        build_xt<<<(unsigned)((total + 255) / 256), 256>>>(x);
    }
    // 2. QKV_T = XT @ Wqkv_t
    BIG0<<<g3(3 * DIM_C, 128, MT, 128, 1), 256>>>(
        XT, rWqkv_t, QKVT, nullptr, nullptr,
        MT, 3 * DIM_C, DIM_C, DIM_C, 3 * DIM_C, 3 * DIM_C,
        0, 0, 0, 0, 0, 0, 1, 1.f);
    // 3. S_T = 0.125 * Q @ K^T  (512 batched 257x257x64), ldc = 272
    SMT<<<g3(NT_T, 64, NT_T, 64, BT_C * HEADS_C), 128>>>(
        QKVT, QKVT + DIM_C, ST, nullptr, nullptr,
        NT_T, NT_T, DH_C, 3 * DIM_C, 3 * DIM_C, STLD,
        (long)NT_T * 3 * DIM_C, DH_C, (long)NT_T * 3 * DIM_C, DH_C,
        (long)HEADS_C * NT_T * STLD, (long)NT_T * STLD,
        HEADS_C, 0.125f);
    // 4. softmax (rounds output)
    softmax1<NT_T, STLD><<<BT_C * HEADS_C * NT_T, 128>>>(ST);
    // 5. O_T = S @ V   (257x64 over K=272; pad cols of S are 0)
    SMN<<<g3(DH_C, 64, NT_T, 64, BT_C * HEADS_C), 128>>>(
        ST, QKVT + 2 * DIM_C, OT, nullptr, nullptr,
        NT_T, DH_C, STLD, STLD, 3 * DIM_C, DIM_C,
        (long)HEADS_C * NT_T * STLD, (long)NT_T * STLD,
        (long)NT_T * 3 * DIM_C, DH_C,
        (long)NT_T * DIM_C, DH_C,
        HEADS_C, 1.f);
    // 6. Y1 = O_T @ Wo_t + XT
    BIGR<<<g3(DIM_C, 128, MT, 128, 1), 256>>>(
        OT, rWo_t, Y1, nullptr, XT,
        MT, DIM_C, DIM_C, DIM_C, DIM_C, DIM_C,
        0, 0, 0, 0, 0, 0, 1, 1.f);
    // 7. gather -> Z
    {
        long total = (long)BS_C * NT_S * DIM_C;
        build_z<<<(unsigned)((total + 255) / 256), 256>>>();
    }
    // 8. QKV_S = Z @ Wqkv_s
    BIG0<<<g3(3 * DIM_C, 128, MS, 128, 1), 256>>>(
        Z, rWqkv_s, QKVS, nullptr, nullptr,
        MS, 3 * DIM_C, DIM_C, DIM_C, 3 * DIM_C, 3 * DIM_C,
        0, 0, 0, 0, 0, 0, 1, 1.f);
    // 9/10. K_c, V_c = E^T @ {K,V}  (2048 batched 128x64 over K=80)
    SMN<<<g3(DH_C, 64, KLIN_C, 64, BS_C * HEADS_C), 128>>>(
        Et, QKVS + DIM_C, KC, nullptr, nullptr,
        KLIN_C, DH_C, ETLD, ETLD, 3 * DIM_C, DH_C,
        0, 0, (long)NT_S * 3 * DIM_C, DH_C,
        (long)HEADS_C * KLIN_C * DH_C, (long)KLIN_C * DH_C,
        HEADS_C, 1.f);
    SMN<<<g3(DH_C, 64, KLIN_C, 64, BS_C * HEADS_C), 128>>>(
        Et, QKVS + 2 * DIM_C, VC, nullptr, nullptr,
        KLIN_C, DH_C, ETLD, ETLD, 3 * DIM_C, DH_C,
        0, 0, (long)NT_S * 3 * DIM_C, DH_C,
        (long)HEADS_C * KLIN_C * DH_C, (long)KLIN_C * DH_C,
        HEADS_C, 1.f);
    // 11. S_S = 0.125 * Q @ K_c^T  (2048 batched 65x128x64)
    SMT<<<g3(KLIN_C, 64, NT_S, 64, BS_C * HEADS_C), 128>>>(
        QKVS, KC, SS, nullptr, nullptr,
        NT_S, KLIN_C, DH_C, 3 * DIM_C, DH_C, KLIN_C,
        (long)NT_S * 3 * DIM_C, DH_C,
        (long)HEADS_C * KLIN_C * DH_C, (long)KLIN_C * DH_C,
        (long)HEADS_C * NT_S * KLIN_C, (long)NT_S * KLIN_C,
        HEADS_C, 0.125f);
    // 12. softmax (rounds)
    softmax1<KLIN_C, KLIN_C><<<BS_C * HEADS_C * NT_S, 128>>>(SS);
    // 13. O_S = S_S @ V_c (65x64x128)
    SMN<<<g3(DH_C, 64, NT_S, 64, BS_C * HEADS_C), 128>>>(
        SS, VC, OS, nullptr, nullptr,
        NT_S, DH_C, KLIN_C, KLIN_C, DH_C, DIM_C,
        (long)HEADS_C * NT_S * KLIN_C, (long)NT_S * KLIN_C,
        (long)HEADS_C * KLIN_C * DH_C, (long)KLIN_C * DH_C,
        (long)NT_S * DIM_C, DH_C,
        HEADS_C, 1.f);
    // 14. Y2 = O_S @ Wo_s + Z
    BIGR<<<g3(DIM_C, 128, MS, 128, 1), 256>>>(
        OS, rWo_s, Y2, nullptr, Z,
        MS, DIM_C, DIM_C, DIM_C, DIM_C, DIM_C,
        0, 0, 0, 0, 0, 0, 1, 1.f);
    // 15. H = gelu(Y2 @ W1 + b1)
    BIGG<<<g3(DFF_C, 128, MS, 128, 1), 256>>>(
        Y2, rW1, H, b1, nullptr,
        MS, DFF_C, DIM_C, DIM_C, DFF_C, DFF_C,
        0, 0, 0, 0, 0, 0, 1, 1.f);
    // 16. out = H @ W2 + b2 + Y2
    BIGBR<<<g3(DIM_C, 128, MS, 128, 1), 256>>>(
        H, rW2, out, b2, Y2,
        MS, DIM_C, DFF_C, DFF_C, DIM_C, DIM_C,
        0, 0, 0, 0, 0, 0, 1, 1.f);
    (void)in_sizes; (void)n_in; (void)out_size;
}

// round 5
// speedup vs baseline: 4.0361x; 1.4784x over previous
#include <cuda_runtime.h>
#include <cuda_fp16.h>
#include <math.h>
#include <stdint.h>

// ---------------------------------------------------------------------------
// TimeSformer block on sm_103 (compute_103 target -> legacy mma.sync only).
// Round 4: all GEMMs on fp16 HMMA (m16n8k16, fp32 accumulate), ldmatrix
// fragment loads, half activations/weights, fp32 residuals & scores.
// ---------------------------------------------------------------------------

#define FRAMES_C  256
#define PATCHES_C 64
#define DIM_C     512
#define HEADS_C   8
#define DH_C      64
#define DFF_C     1024
#define KLIN_C    128
#define NT_T      257
#define NT_S      65
#define BT_C      64
#define BS_C      256
#define STLD      272          // padded key-dim for temporal scores/probs
#define ETLD      80           // padded token-dim for E^T

// ------------------------- scratch (device globals) ------------------------
// zero-initialized at load; pad regions never written -> stay exactly 0.
__device__ __half hXT  [((size_t)BT_C * NT_T + 64) * DIM_C];
__device__ float  fXT  [(size_t)BT_C * NT_T * DIM_C];
__device__ __half hQKVT[((size_t)BT_C * NT_T + 16) * 3 * DIM_C];
__device__ float  fST  [(size_t)BT_C * HEADS_C * NT_T * STLD];
__device__ __half hPT  [(size_t)BT_C * HEADS_C * NT_T * STLD];
__device__ __half hOT  [((size_t)BT_C * NT_T + 64) * DIM_C];
__device__ float  fY1  [(size_t)BT_C * NT_T * DIM_C];
__device__ __half hZ   [((size_t)BS_C * NT_S + 64) * DIM_C];
__device__ float  fZ   [(size_t)BS_C * NT_S * DIM_C];
__device__ __half hQKVS[((size_t)BS_C * NT_S + 16) * 3 * DIM_C];
__device__ __half hEt  [(size_t)KLIN_C * ETLD];
__device__ __half hKC  [(size_t)BS_C * HEADS_C * KLIN_C * DH_C];
__device__ __half hVC  [(size_t)BS_C * HEADS_C * KLIN_C * DH_C];
__device__ float  fSS  [(size_t)BS_C * HEADS_C * NT_S * KLIN_C];
__device__ __half hPS  [(size_t)BS_C * HEADS_C * NT_S * KLIN_C];
__device__ __half hOS  [((size_t)BS_C * NT_S + 64) * DIM_C];
__device__ float  fY2  [(size_t)BS_C * NT_S * DIM_C];
__device__ __half hY2  [((size_t)BS_C * NT_S + 64) * DIM_C];
__device__ __half hH   [((size_t)BS_C * NT_S + 64) * DFF_C];
// transposed (N,K) fp16 weights
__device__ __half tWqkv_t[(size_t)3 * DIM_C * DIM_C];
__device__ __half tWo_t  [(size_t)DIM_C * DIM_C];
__device__ __half tWqkv_s[(size_t)3 * DIM_C * DIM_C];
__device__ __half tWo_s  [(size_t)DIM_C * DIM_C];
__device__ __half tW1    [(size_t)DFF_C * DIM_C];
__device__ __half tW2    [(size_t)DIM_C * DFF_C];

// ------------------------------ helpers -------------------------------------
__device__ __forceinline__ uint32_t smaddr(const void* p) {
    uint32_t a;
    asm("{ .reg .u64 t; cvta.to.shared.u64 t, %1; cvt.u32.u64 %0, t; }" : "=r"(a) : "l"(p));
    return a;
}
__device__ __forceinline__ void ldmx4(uint32_t& r0, uint32_t& r1, uint32_t& r2, uint32_t& r3,
                                      uint32_t a) {
    asm volatile("ldmatrix.sync.aligned.m8n8.x4.shared.b16 {%0,%1,%2,%3}, [%4];"
                 : "=r"(r0), "=r"(r1), "=r"(r2), "=r"(r3) : "r"(a));
}
__device__ __forceinline__ void mma16816(float c[4], const uint32_t a[4], const uint32_t b[2]) {
    asm volatile("mma.sync.aligned.m16n8k16.row.col.f32.f16.f16.f32 "
                 "{%0,%1,%2,%3},{%4,%5,%6,%7},{%8,%9},{%0,%1,%2,%3};"
                 : "+f"(c[0]), "+f"(c[1]), "+f"(c[2]), "+f"(c[3])
                 : "r"(a[0]), "r"(a[1]), "r"(a[2]), "r"(a[3]), "r"(b[0]), "r"(b[1]));
}

// ------------------------------- prep kernels -------------------------------
// dst(N,K) half = round(src(K,N))^T
__global__ void transpose_round(__half* __restrict__ dst, const float* __restrict__ src,
                                int K, int N) {
    int i = blockIdx.x * blockDim.x + threadIdx.x;
    if (i >= N * K) return;
    int k = i % K, n = i / K;
    dst[i] = __float2half_rn(src[(long)k * N + n]);
}
__global__ void build_xt(const float* __restrict__ x) {
    long idx = (long)blockIdx.x * blockDim.x + threadIdx.x;
    const long total = (long)BT_C * NT_T * DIM_C;
    if (idx >= total) return;
    int d = (int)(idx % DIM_C);
    long r = idx / DIM_C;
    int t = (int)(r % NT_T);
    int p = (int)(r / NT_T);
    float v;
    if (t == 0) v = x[d];
    else        v = x[(long)(1 + (t - 1) * PATCHES_C + p) * DIM_C + d];
    hXT[idx] = __float2half_rn(v);
    fXT[idx] = v;
}
__global__ void build_z() {
    long idx = (long)blockIdx.x * blockDim.x + threadIdx.x;
    const long total = (long)BS_C * NT_S * DIM_C;
    if (idx >= total) return;
    int d = (int)(idx % DIM_C);
    long r = idx / DIM_C;
    int s = (int)(r % NT_S);
    int f = (int)(r / NT_S);
    float v;
    if (s == 0) v = fY1[(long)(f & 63) * NT_T * DIM_C + d];
    else        v = fY1[(long)(s - 1) * NT_T * DIM_C + (long)(1 + f) * DIM_C + d];
    hZ[idx] = __float2half_rn(v);
    fZ[idx] = v;
}
__global__ void transpose_E(const float* __restrict__ E) {
    int i = blockIdx.x * blockDim.x + threadIdx.x;
    if (i >= KLIN_C * NT_S) return;
    int j = i % NT_S, kc = i / NT_S;
    hEt[kc * ETLD + j] = __float2half_rn(E[j * KLIN_C + kc]);
}

// ---------------- single-pass softmax: f32 scores -> f16 probs --------------
template<int NC, int LD>
__global__ void softmaxh(const float* __restrict__ Sf, __half* __restrict__ Ph) {
    constexpr int NTHR = 128;
    constexpr int PER = (NC + NTHR - 1) / NTHR;
    long row = blockIdx.x;
    const float* p = Sf + row * (long)LD;
    __half* q = Ph + row * (long)LD;
    int tid = threadIdx.x, lane = tid & 31, warp = tid >> 5;
    __shared__ float red[4];
    float v[PER];
    float m = -1e30f;
    #pragma unroll
    for (int i = 0; i < PER; i++) {
        int c = tid + i * NTHR;
        v[i] = (c < NC) ? p[c] : -1e30f;
        m = fmaxf(m, v[i]);
    }
    #pragma unroll
    for (int s = 16; s > 0; s >>= 1) m = fmaxf(m, __shfl_xor_sync(0xffffffffu, m, s));
    if (lane == 0) red[warp] = m;
    __syncthreads();
    m = fmaxf(fmaxf(red[0], red[1]), fmaxf(red[2], red[3]));
    float sum = 0.f;
    #pragma unroll
    for (int i = 0; i < PER; i++) {
        v[i] = __expf(v[i] - m);
        int c = tid + i * NTHR;
        if (c < NC) sum += v[i];
    }
    #pragma unroll
    for (int s = 16; s > 0; s >>= 1) sum += __shfl_xor_sync(0xffffffffu, sum, s);
    __syncthreads();
    if (lane == 0) red[warp] = sum;
    __syncthreads();
    float inv = 1.f / (red[0] + red[1] + red[2] + red[3]);
    #pragma unroll
    for (int i = 0; i < PER; i++) {
        int c = tid + i * NTHR;
        if (c < NC) q[c] = __float2half_rn(v[i] * inv);
    }
}

// =================== big fp16 GEMM: C = A(M,K) @ Bt(N,K)^T ==================
// BM=128, BN=128, BK=32, 8 warps (2x4), warp tile 64x32 (MT=4, NT=4).
// EPI: 0 none | 1 bias+gelu | 2 bias+residual | 3 residual
// OUT: 0 half only | 1 float only | 2 both
template<int EPI, int OUT>
__global__ void __launch_bounds__(256)
hgemm_big(const __half* __restrict__ A, const __half* __restrict__ Bt,
          __half* __restrict__ Ch, float* __restrict__ Cf,
          const float* __restrict__ bias, const float* __restrict__ Rf,
          int M, int N, int K, int ldc)
{
    constexpr int BM = 128, BN = 128, BK = 32, LDS_ = BK + 8;
    __shared__ __half As[2][BM][LDS_];
    __shared__ __half Bs[2][BN][LDS_];

    const int tid = threadIdx.x, lane = tid & 31, warp = tid >> 5;
    const int wr = warp >> 2, wc = warp & 3;
    const int bm = blockIdx.y * BM, bn = blockIdx.x * BN;
    A  += (long)bm * K;
    Bt += (long)bn * K;

    float c[4][4][4];
    #pragma unroll
    for (int i = 0; i < 4; i++)
        #pragma unroll
        for (int j = 0; j < 4; j++)
            #pragma unroll
            for (int q = 0; q < 4; q++) c[i][j][q] = 0.f;

    float4 a4[2], b4[2];
    auto loadg = [&](int t) {
        int k0 = t * BK;
        #pragma unroll
        for (int i = 0; i < 2; i++) {
            int s = tid + i * 256;
            int row = s >> 2, seg = s & 3;
            a4[i] = (bm + row < M) ? *(const float4*)(A + (long)row * K + k0 + seg * 8)
                                   : make_float4(0.f, 0.f, 0.f, 0.f);
        }
        #pragma unroll
        for (int i = 0; i < 2; i++) {
            int s = tid + i * 256;
            int row = s >> 2, seg = s & 3;
            b4[i] = *(const float4*)(Bt + (long)row * K + k0 + seg * 8);
        }
    };
    auto stores = [&](int buf) {
        #pragma unroll
        for (int i = 0; i < 2; i++) {
            int s = tid + i * 256;
            int row = s >> 2, seg = s & 3;
            *(float4*)&As[buf][row][seg * 8] = a4[i];
        }
        #pragma unroll
        for (int i = 0; i < 2; i++) {
            int s = tid + i * 256;
            int row = s >> 2, seg = s & 3;
            *(float4*)&Bs[buf][row][seg * 8] = b4[i];
        }
    };
    auto comp = [&](int cu) {
        #pragma unroll
        for (int ks = 0; ks < 2; ks++) {
            int k0 = ks * 16;
            uint32_t af[4][4], bf[4][2];
            #pragma unroll
            for (int mt = 0; mt < 4; mt++) {
                uint32_t ad = smaddr(&As[cu][wr * 64 + mt * 16 + (lane & 15)]
                                        [k0 + ((lane & 16) ? 8 : 0)]);
                ldmx4(af[mt][0], af[mt][1], af[mt][2], af[mt][3], ad);
            }
            #pragma unroll
            for (int p = 0; p < 2; p++) {
                int n0 = wc * 32 + p * 16;
                uint32_t bd = smaddr(&Bs[cu][n0 + (lane & 7) + ((lane & 16) ? 8 : 0)]
                                        [k0 + (lane & 8)]);
                uint32_t r0, r1, r2, r3;
                ldmx4(r0, r1, r2, r3, bd);
                bf[2 * p][0] = r0; bf[2 * p][1] = r1;
                bf[2 * p + 1][0] = r2; bf[2 * p + 1][1] = r3;
            }
            #pragma unroll
            for (int mt = 0; mt < 4; mt++)
                #pragma unroll
                for (int nt = 0; nt < 4; nt++)
                    mma16816(c[mt][nt], af[mt], bf[nt]);
        }
    };

    int ntl = K / BK;
    loadg(0);
    stores(0);
    __syncthreads();
    int cu = 0;
    for (int t = 0; t < ntl; t++) {
        if (t + 1 < ntl) loadg(t + 1);
        comp(cu);
        if (t + 1 < ntl) stores(cu ^ 1);
        __syncthreads();
        cu ^= 1;
    }

    #pragma unroll
    for (int mt = 0; mt < 4; mt++) {
        #pragma unroll
        for (int nt = 0; nt < 4; nt++) {
            int r0 = bm + wr * 64 + mt * 16 + (lane >> 2);
            int col = bn + wc * 32 + nt * 8 + (lane & 3) * 2;
            #pragma unroll
            for (int h = 0; h < 2; h++) {
                int r = r0 + h * 8;
                if (r >= M) continue;
                #pragma unroll
                for (int j = 0; j < 2; j++) {
                    int gc = col + j;
                    float v = c[mt][nt][h * 2 + j];
                    if constexpr (EPI == 1) {
                        v += bias[gc];
                        v = 0.5f * v * (1.f + erff(v * 0.70710678118654752f));
                    } else if constexpr (EPI == 2) {
                        v += bias[gc] + Rf[(long)r * ldc + gc];
                    } else if constexpr (EPI == 3) {
                        v += Rf[(long)r * ldc + gc];
                    }
                    if constexpr (OUT == 0) {
                        Ch[(long)r * ldc + gc] = __float2half_rn(v);
                    } else if constexpr (OUT == 1) {
                        Cf[(long)r * ldc + gc] = v;
                    } else {
                        Cf[(long)r * ldc + gc] = v;
                        Ch[(long)r * ldc + gc] = __float2half_rn(v);
                    }
                }
            }
        }
    }
}

// ============== small batched fp16 GEMM (attention), 64x64x16 ===============
// TRB: B global is (N,K) row-major (direct). !TRB: B global is (K,N) ->
// transpose during staging. OUTH: write half C, else float C (with alpha).
template<bool TRB, bool OUTH>
__global__ void __launch_bounds__(128)
hgemm_sm(const __half* __restrict__ A, const __half* __restrict__ B,
         void* __restrict__ Cv,
         int M, int N, int K, int lda, int ldb, int ldc,
         long soA, long siA, long soB, long siB, long soC, long siC,
         int NI, float alpha)
{
    constexpr int BM = 64, BN = 64, BK = 16, LDS_ = BK + 8;
    __shared__ __half As[2][BM][LDS_];
    __shared__ __half Bs[2][BN][LDS_];

    int e = blockIdx.z;
    int o = e / NI, ii = e - o * NI;
    A += o * soA + (long)ii * siA;
    B += o * soB + (long)ii * siB;

    const int tid = threadIdx.x, lane = tid & 31, warp = tid >> 5;
    const int wr = warp >> 1, wc = warp & 1;       // 2x2 warps, tile 32x32
    const int bm = blockIdx.y * BM, bn = blockIdx.x * BN;

    float c[2][4][4];
    #pragma unroll
    for (int i = 0; i < 2; i++)
        #pragma unroll
        for (int j = 0; j < 4; j++)
            #pragma unroll
            for (int q = 0; q < 4; q++) c[i][j][q] = 0.f;

    float4 a4, b4;
    auto loadg = [&](int t) {
        int k0 = t * BK;
        {
            int row = tid >> 1, seg = tid & 1;
            int gr = bm + row;
            a4 = (gr < M) ? *(const float4*)(A + (long)gr * lda + k0 + seg * 8)
                          : make_float4(0.f, 0.f, 0.f, 0.f);
        }
        if constexpr (TRB) {
            int row = tid >> 1, seg = tid & 1;
            int gc = bn + row;
            b4 = (gc < N) ? *(const float4*)(B + (long)gc * ldb + k0 + seg * 8)
                          : make_float4(0.f, 0.f, 0.f, 0.f);
        } else {
            int kk = tid >> 3, nseg = tid & 7;
            b4 = *(const float4*)(B + (long)(t * BK + kk) * ldb + bn + nseg * 8);
        }
    };
    auto stores = [&](int buf) {
        {
            int row = tid >> 1, seg = tid & 1;
            *(float4*)&As[buf][row][seg * 8] = a4;
        }
        if constexpr (TRB) {
            int row = tid >> 1, seg = tid & 1;
            *(float4*)&Bs[buf][row][seg * 8] = b4;
        } else {
            int kk = tid >> 3, nseg = tid & 7;
            const __half* hp = (const __half*)&b4;
            #pragma unroll
            for (int j = 0; j < 8; j++) Bs[buf][nseg * 8 + j][kk] = hp[j];
        }
    };
    auto comp = [&](int cu) {
        uint32_t af[2][4], bf[4][2];
        #pragma unroll
        for (int mt = 0; mt < 2; mt++) {
            uint32_t ad = smaddr(&As[cu][wr * 32 + mt * 16 + (lane & 15)]
                                    [((lane & 16) ? 8 : 0)]);
            ldmx4(af[mt][0], af[mt][1], af[mt][2], af[mt][3], ad);
        }
        #pragma unroll
        for (int p = 0; p < 2; p++) {
            int n0 = wc * 32 + p * 16;
            uint32_t bd = smaddr(&Bs[cu][n0 + (lane & 7) + ((lane & 16) ? 8 : 0)]
                                    [(lane & 8)]);
            uint32_t r0, r1, r2, r3;
            ldmx4(r0, r1, r2, r3, bd);
            bf[2 * p][0] = r0; bf[2 * p][1] = r1;
            bf[2 * p + 1][0] = r2; bf[2 * p + 1][1] = r3;
        }
        #pragma unroll
        for (int mt = 0; mt < 2; mt++)
            #pragma unroll
            for (int nt = 0; nt < 4; nt++)
                mma16816(c[mt][nt], af[mt], bf[nt]);
    };

    int ntl = K / BK;
    loadg(0);
    stores(0);
    __syncthreads();
    int cu = 0;
    for (int t = 0; t < ntl; t++) {
        if (t + 1 < ntl) loadg(t + 1);
        comp(cu);
        if (t + 1 < ntl) stores(cu ^ 1);
        __syncthreads();
        cu ^= 1;
    }

    __half* Chh = (__half*)Cv;
    float*  Cff = (float*)Cv;
    long cbase = o * soC + (long)ii * siC;
    #pragma unroll
    for (int mt = 0; mt < 2; mt++) {
        #pragma unroll
        for (int nt = 0; nt < 4; nt++) {
            int r0 = bm + wr * 32 + mt * 16 + (lane >> 2);
            int col = bn + wc * 32 + nt * 8 + (lane & 3) * 2;
            #pragma unroll
            for (int h = 0; h < 2; h++) {
                int r = r0 + h * 8;
                if (r >= M) continue;
                #pragma unroll
                for (int j = 0; j < 2; j++) {
                    int gc = col + j;
                    if (gc >= N) continue;
                    float v = c[mt][nt][h * 2 + j] * alpha;
                    if constexpr (OUTH) Chh[cbase + (long)r * ldc + gc] = __float2half_rn(v);
                    else                Cff[cbase + (long)r * ldc + gc] = v;
                }
            }
        }
    }
}

#define SMT hgemm_sm<true,  false>      // scores: Q@K^T -> fp32
#define SMN hgemm_sm<false, true>       // P@V / Et@X -> fp16

static inline dim3 g3(int N, int BN, int M, int BM, int Z) {
    return dim3((N + BN - 1) / BN, (M + BM - 1) / BM, Z);
}

extern "C" void kernel_launch(void* const* d_in, const int* in_sizes, int n_in,
                              void* d_out, int out_size) {
    const float* x      = (const float*)d_in[0];
    const float* Wqkv_t = (const float*)d_in[1];
    const float* Wo_t   = (const float*)d_in[2];
    const float* Wqkv_s = (const float*)d_in[3];
    const float* Wo_s   = (const float*)d_in[4];
    const float* E      = (const float*)d_in[5];
    const float* W1     = (const float*)d_in[6];
    const float* b1     = (const float*)d_in[7];
    const float* W2     = (const float*)d_in[8];
    const float* b2     = (const float*)d_in[9];
    float* out = (float*)d_out;

    __half *pXT, *pQKVT, *pPT, *pOT, *pZ, *pQKVS, *pEt, *pKC, *pVC, *pPS, *pOS, *pY2h, *pH;
    float  *pfXT, *pfST, *pfY1, *pfZ, *pfSS, *pfY2;
    __half *ptWqkv_t, *ptWo_t, *ptWqkv_s, *ptWo_s, *ptW1, *ptW2;
    cudaGetSymbolAddress((void**)&pXT,   hXT);
    cudaGetSymbolAddress((void**)&pfXT,  fXT);
    cudaGetSymbolAddress((void**)&pQKVT, hQKVT);
    cudaGetSymbolAddress((void**)&pfST,  fST);
    cudaGetSymbolAddress((void**)&pPT,   hPT);
    cudaGetSymbolAddress((void**)&pOT,   hOT);
    cudaGetSymbolAddress((void**)&pfY1,  fY1);
    cudaGetSymbolAddress((void**)&pZ,    hZ);
    cudaGetSymbolAddress((void**)&pfZ,   fZ);
    cudaGetSymbolAddress((void**)&pQKVS, hQKVS);
    cudaGetSymbolAddress((void**)&pEt,   hEt);
    cudaGetSymbolAddress((void**)&pKC,   hKC);
    cudaGetSymbolAddress((void**)&pVC,   hVC);
    cudaGetSymbolAddress((void**)&pfSS,  fSS);
    cudaGetSymbolAddress((void**)&pPS,   hPS);
    cudaGetSymbolAddress((void**)&pOS,   hOS);
    cudaGetSymbolAddress((void**)&pfY2,  fY2);
    cudaGetSymbolAddress((void**)&pY2h,  hY2);
    cudaGetSymbolAddress((void**)&pH,    hH);
    cudaGetSymbolAddress((void**)&ptWqkv_t, tWqkv_t);
    cudaGetSymbolAddress((void**)&ptWo_t,   tWo_t);
    cudaGetSymbolAddress((void**)&ptWqkv_s, tWqkv_s);
    cudaGetSymbolAddress((void**)&ptWo_s,   tWo_s);
    cudaGetSymbolAddress((void**)&ptW1,     tW1);
    cudaGetSymbolAddress((void**)&ptW2,     tW2);

    const int MT = BT_C * NT_T;   // 16448
    const int MS = BS_C * NT_S;   // 16640
    const int MT_T = (MT + 127) / 128;  // 129
    const int MS_T = (MS + 127) / 128;  // 130

    // 0. weight prep
    transpose_round<<<(3 * DIM_C * DIM_C + 255) / 256, 256>>>(ptWqkv_t, Wqkv_t, DIM_C, 3 * DIM_C);
    transpose_round<<<(DIM_C * DIM_C + 255) / 256, 256>>>(ptWo_t, Wo_t, DIM_C, DIM_C);
    transpose_round<<<(3 * DIM_C * DIM_C + 255) / 256, 256>>>(ptWqkv_s, Wqkv_s, DIM_C, 3 * DIM_C);
    transpose_round<<<(DIM_C * DIM_C + 255) / 256, 256>>>(ptWo_s, Wo_s, DIM_C, DIM_C);
    transpose_round<<<(DIM_C * DFF_C + 255) / 256, 256>>>(ptW1, W1, DIM_C, DFF_C);
    transpose_round<<<(DFF_C * DIM_C + 255) / 256, 256>>>(ptW2, W2, DFF_C, DIM_C);
    transpose_E<<<(KLIN_C * NT_S + 255) / 256, 256>>>(E);

    // 1. gather
    build_xt<<<(unsigned)(((long)BT_C * NT_T * DIM_C + 255) / 256), 256>>>(x);

    // 2. QKV_T = XT @ Wqkv_t
    hgemm_big<0, 0><<<dim3(12, MT_T), 256>>>(
        pXT, ptWqkv_t, pQKVT, nullptr, nullptr, nullptr, MT, 3 * DIM_C, DIM_C, 3 * DIM_C);
    // 3. S_T = 0.125 * Q @ K^T  (512 batched 257x257x64) -> fp32 scores
    SMT<<<g3(NT_T, 64, NT_T, 64, BT_C * HEADS_C), 128>>>(
        pQKVT, pQKVT + DIM_C, pfST,
        NT_T, NT_T, DH_C, 3 * DIM_C, 3 * DIM_C, STLD,
        (long)NT_T * 3 * DIM_C, DH_C, (long)NT_T * 3 * DIM_C, DH_C,
        (long)HEADS_C * NT_T * STLD, (long)NT_T * STLD,
        HEADS_C, 0.125f);
    // 4. softmax -> fp16 probs
    softmaxh<NT_T, STLD><<<BT_C * HEADS_C * NT_T, 128>>>(pfST, pPT);
    // 5. O_T = P @ V   (K = 272, pad probs are 0)
    SMN<<<g3(DH_C, 64, NT_T, 64, BT_C * HEADS_C), 128>>>(
        pPT, pQKVT + 2 * DIM_C, pOT,
        NT_T, DH_C, STLD, STLD, 3 * DIM_C, DIM_C,
        (long)HEADS_C * NT_T * STLD, (long)NT_T * STLD,
        (long)NT_T * 3 * DIM_C, DH_C,
        (long)NT_T * DIM_C, DH_C,
        HEADS_C, 1.f);
    // 6. Y1 = O_T @ Wo_t + XT (fp32 residual, fp32 out)
    hgemm_big<3, 1><<<dim3(4, MT_T), 256>>>(
        pOT, ptWo_t, nullptr, pfY1, nullptr, pfXT, MT, DIM_C, DIM_C, DIM_C);
    // 7. gather
    build_z<<<(unsigned)(((long)BS_C * NT_S * DIM_C + 255) / 256), 256>>>();
    // 8. QKV_S = Z @ Wqkv_s
    hgemm_big<0, 0><<<dim3(12, MS_T), 256>>>(
        pZ, ptWqkv_s, pQKVS, nullptr, nullptr, nullptr, MS, 3 * DIM_C, DIM_C, 3 * DIM_C);
    // 9/10. K_c, V_c = E^T @ {K,V}  (2048 batched 128x64, K = 80 padded)
    SMN<<<g3(DH_C, 64, KLIN_C, 64, BS_C * HEADS_C), 128>>>(
        pEt, pQKVS + DIM_C, pKC,
        KLIN_C, DH_C, ETLD, ETLD, 3 * DIM_C, DH_C,
        0, 0, (long)NT_S * 3 * DIM_C, DH_C,
        (long)HEADS_C * KLIN_C * DH_C, (long)KLIN_C * DH_C,
        HEADS_C, 1.f);
    SMN<<<g3(DH_C, 64, KLIN_C, 64, BS_C * HEADS_C), 128>>>(
        pEt, pQKVS + 2 * DIM_C, pVC,
        KLIN_C, DH_C, ETLD, ETLD, 3 * DIM_C, DH_C,
        0, 0, (long)NT_S * 3 * DIM_C, DH_C,
        (long)HEADS_C * KLIN_C * DH_C, (long)KLIN_C * DH_C,
        HEADS_C, 1.f);
    // 11. S_S = 0.125 * Q @ K_c^T -> fp32 scores
    SMT<<<g3(KLIN_C, 64, NT_S, 64, BS_C * HEADS_C), 128>>>(
        pQKVS, pKC, pfSS,
        NT_S, KLIN_C, DH_C, 3 * DIM_C, DH_C, KLIN_C,
        (long)NT_S * 3 * DIM_C, DH_C,
        (long)HEADS_C * KLIN_C * DH_C, (long)KLIN_C * DH_C,
        (long)HEADS_C * NT_S * KLIN_C, (long)NT_S * KLIN_C,
        HEADS_C, 0.125f);
    // 12. softmax -> fp16 probs
    softmaxh<KLIN_C, KLIN_C><<<BS_C * HEADS_C * NT_S, 128>>>(pfSS, pPS);
    // 13. O_S = P_S @ V_c
    SMN<<<g3(DH_C, 64, NT_S, 64, BS_C * HEADS_C), 128>>>(
        pPS, pVC, pOS,
        NT_S, DH_C, KLIN_C, KLIN_C, DH_C, DIM_C,
        (long)HEADS_C * NT_S * KLIN_C, (long)NT_S * KLIN_C,
        (long)HEADS_C * KLIN_C * DH_C, (long)KLIN_C * DH_C,
        (long)NT_S * DIM_C, DH_C,
        HEADS_C, 1.f);
    // 14. Y2 = O_S @ Wo_s + Z  (fp32 + fp16 out)
    hgemm_big<3, 2><<<dim3(4, MS_T), 256>>>(
        pOS, ptWo_s, pY2h, pfY2, nullptr, pfZ, MS, DIM_C, DIM_C, DIM_C);
    // 15. H = gelu(Y2 @ W1 + b1)
    hgemm_big<1, 0><<<dim3(8, MS_T), 256>>>(
        pY2h, ptW1, pH, nullptr, b1, nullptr, MS, DFF_C, DIM_C, DFF_C);
    // 16. out = H @ W2 + b2 + Y2 (fp32)
    hgemm_big<2, 1><<<dim3(4, MS_T), 256>>>(
        pH, ptW2, nullptr, out, b2, pfY2, MS, DIM_C, DFF_C, DIM_C);
    (void)in_sizes; (void)n_in; (void)out_size;
}

// round 9
// speedup vs baseline: 4.4013x; 1.0905x over previous
#include <cuda_runtime.h>
#include <cuda_fp16.h>
#include <math.h>
#include <stdint.h>

// ---------------------------------------------------------------------------
// TimeSformer block, sm_103 legacy-mma path. Round 7:
//   * FIX: hgemm_sm row-tile offset (blockIdx.y) — R5/R6 left KC/VC rows
//     64..127 unwritten (zeros), causing the 1.9e-3 failure.
//   * fused attention kernels with fp32 smem scores, in-place fp16 probs
//   * big weight GEMMs fp16 HMMA 128x128x32 + ldmatrix
// ---------------------------------------------------------------------------

#define FRAMES_C  256
#define PATCHES_C 64
#define DIM_C     512
#define HEADS_C   8
#define DH_C      64
#define DFF_C     1024
#define KLIN_C    128
#define NT_T      257
#define NT_S      65
#define BT_C      64
#define BS_C      256
#define ETLD      80
#define SFLD_T    276      // fp32 score row stride (temporal)
#define SFLD_S    132      // fp32 score row stride (spatial)

// ------------------------- scratch (device globals) ------------------------
__device__ __half hXT  [((size_t)BT_C * NT_T + 64) * DIM_C];
__device__ float  fXT  [(size_t)BT_C * NT_T * DIM_C];
__device__ __half hQKVT[((size_t)BT_C * NT_T + 16) * 3 * DIM_C];
__device__ __half hOT  [((size_t)BT_C * NT_T + 64) * DIM_C];
__device__ float  fY1  [(size_t)BT_C * NT_T * DIM_C];
__device__ __half hZ   [((size_t)BS_C * NT_S + 64) * DIM_C];
__device__ float  fZ   [(size_t)BS_C * NT_S * DIM_C];
__device__ __half hQKVS[((size_t)BS_C * NT_S + 16) * 3 * DIM_C];
__device__ __half hEt  [(size_t)KLIN_C * ETLD];
__device__ __half hKC  [(size_t)BS_C * HEADS_C * KLIN_C * DH_C];
__device__ __half hVC  [(size_t)BS_C * HEADS_C * KLIN_C * DH_C];
__device__ __half hOS  [((size_t)BS_C * NT_S + 64) * DIM_C];
__device__ float  fY2  [(size_t)BS_C * NT_S * DIM_C];
__device__ __half hY2  [((size_t)BS_C * NT_S + 64) * DIM_C];
__device__ __half hH   [((size_t)BS_C * NT_S + 64) * DFF_C];
__device__ __half tWqkv_t[(size_t)3 * DIM_C * DIM_C];
__device__ __half tWo_t  [(size_t)DIM_C * DIM_C];
__device__ __half tWqkv_s[(size_t)3 * DIM_C * DIM_C];
__device__ __half tWo_s  [(size_t)DIM_C * DIM_C];
__device__ __half tW1    [(size_t)DFF_C * DIM_C];
__device__ __half tW2    [(size_t)DIM_C * DFF_C];

// ------------------------------ helpers -------------------------------------
__device__ __forceinline__ uint32_t smaddr(const void* p) {
    uint32_t a;
    asm("{ .reg .u64 t; cvta.to.shared.u64 t, %1; cvt.u32.u64 %0, t; }" : "=r"(a) : "l"(p));
    return a;
}
__device__ __forceinline__ void ldmx4(uint32_t& r0, uint32_t& r1, uint32_t& r2, uint32_t& r3,
                                      uint32_t a) {
    asm volatile("ldmatrix.sync.aligned.m8n8.x4.shared.b16 {%0,%1,%2,%3}, [%4];"
                 : "=r"(r0), "=r"(r1), "=r"(r2), "=r"(r3) : "r"(a));
}
__device__ __forceinline__ void ldmx4t(uint32_t& r0, uint32_t& r1, uint32_t& r2, uint32_t& r3,
                                       uint32_t a) {
    asm volatile("ldmatrix.sync.aligned.m8n8.x4.trans.shared.b16 {%0,%1,%2,%3}, [%4];"
                 : "=r"(r0), "=r"(r1), "=r"(r2), "=r"(r3) : "r"(a));
}
__device__ __forceinline__ void mma16816(float c[4], const uint32_t a[4], const uint32_t b[2]) {
    asm volatile("mma.sync.aligned.m16n8k16.row.col.f32.f16.f16.f32 "
                 "{%0,%1,%2,%3},{%4,%5,%6,%7},{%8,%9},{%0,%1,%2,%3};"
                 : "+f"(c[0]), "+f"(c[1]), "+f"(c[2]), "+f"(c[3])
                 : "r"(a[0]), "r"(a[1]), "r"(a[2]), "r"(a[3]), "r"(b[0]), "r"(b[1]));
}

// ------------------------------- prep kernels -------------------------------
__global__ void transpose_round(__half* __restrict__ dst, const float* __restrict__ src,
                                int K, int N) {
    int i = blockIdx.x * blockDim.x + threadIdx.x;
    if (i >= N * K) return;
    int k = i % K, n = i / K;
    dst[i] = __float2half_rn(src[(long)k * N + n]);
}
__global__ void build_xt(const float* __restrict__ x) {
    long idx = (long)blockIdx.x * blockDim.x + threadIdx.x;
    const long total = (long)BT_C * NT_T * DIM_C;
    if (idx >= total) return;
    int d = (int)(idx % DIM_C);
    long r = idx / DIM_C;
    int t = (int)(r % NT_T);
    int p = (int)(r / NT_T);
    float v;
    if (t == 0) v = x[d];
    else        v = x[(long)(1 + (t - 1) * PATCHES_C + p) * DIM_C + d];
    hXT[idx] = __float2half_rn(v);
    fXT[idx] = v;
}
__global__ void build_z() {
    long idx = (long)blockIdx.x * blockDim.x + threadIdx.x;
    const long total = (long)BS_C * NT_S * DIM_C;
    if (idx >= total) return;
    int d = (int)(idx % DIM_C);
    long r = idx / DIM_C;
    int s = (int)(r % NT_S);
    int f = (int)(r / NT_S);
    float v;
    if (s == 0) v = fY1[(long)(f & 63) * NT_T * DIM_C + d];
    else        v = fY1[(long)(s - 1) * NT_T * DIM_C + (long)(1 + f) * DIM_C + d];
    hZ[idx] = __float2half_rn(v);
    fZ[idx] = v;
}
__global__ void transpose_E(const float* __restrict__ E) {
    int i = blockIdx.x * blockDim.x + threadIdx.x;
    if (i >= KLIN_C * NT_S) return;
    int j = i % NT_S, kc = i / NT_S;
    hEt[kc * ETLD + j] = __float2half_rn(E[j * KLIN_C + kc]);
}

// ================= fused temporal attention (257 keys, dh=64) ===============
#define ATNT_SMEM (9216 + 9216 + 39168 + 64 * SFLD_T * 4)
__global__ void __launch_bounds__(256, 1)
attn_t() {
    extern __shared__ char sm[];
    __half* Qs = (__half*)sm;
    __half* Ks = (__half*)(sm + 9216);
    __half* Vs = (__half*)(sm + 18432);
    float*  SPf = (float*)(sm + 57600);
    const int tid = threadIdx.x, lane = tid & 31, warp = tid >> 5;
    const int bm = blockIdx.x * 64;
    const int b = blockIdx.y >> 3, h = blockIdx.y & 7;
    const __half* Qg = hQKVT + (size_t)b * NT_T * (3 * DIM_C) + h * 64;
    const __half* Kg = Qg + DIM_C;
    const __half* Vg = Qg + 2 * DIM_C;
    const float4 z4 = make_float4(0.f, 0.f, 0.f, 0.f);

    #pragma unroll
    for (int i = tid; i < 512; i += 256) {                   // Q 64x64
        int r = i >> 3, s = i & 7;
        int gr = bm + r;
        float4 v = (gr < NT_T) ? *(const float4*)(Qg + (size_t)gr * 1536 + s * 8) : z4;
        *(float4*)&Qs[r * 72 + s * 8] = v;
    }
    for (int i = tid; i < 2176; i += 256) {                  // V 272x64
        int r = i >> 3, s = i & 7;
        float4 v = (r < NT_T) ? *(const float4*)(Vg + (size_t)r * 1536 + s * 8) : z4;
        *(float4*)&Vs[r * 72 + s * 8] = v;
    }
    __syncthreads();

    const int wr = warp >> 2, wc = warp & 3;
    uint32_t aq[2][4][4];
    #pragma unroll
    for (int mt = 0; mt < 2; mt++)
        #pragma unroll
        for (int ks = 0; ks < 4; ks++) {
            uint32_t ad = smaddr(&Qs[(wr * 32 + mt * 16 + (lane & 15)) * 72 +
                                     ks * 16 + ((lane & 16) ? 8 : 0)]);
            ldmx4(aq[mt][ks][0], aq[mt][ks][1], aq[mt][ks][2], aq[mt][ks][3], ad);
        }

    for (int kt = 0; kt < 5; kt++) {
        __syncthreads();
        #pragma unroll
        for (int i = tid; i < 512; i += 256) {               // K tile 64x64
            int r = i >> 3, s = i & 7;
            int key = kt * 64 + r;
            float4 v = (key < NT_T) ? *(const float4*)(Kg + (size_t)key * 1536 + s * 8) : z4;
            *(float4*)&Ks[r * 72 + s * 8] = v;
        }
        __syncthreads();
        float c[2][2][4];
        #pragma unroll
        for (int mt = 0; mt < 2; mt++)
            #pragma unroll
            for (int nt = 0; nt < 2; nt++)
                #pragma unroll
                for (int q = 0; q < 4; q++) c[mt][nt][q] = 0.f;
        #pragma unroll
        for (int ks = 0; ks < 4; ks++) {
            uint32_t r0, r1, r2, r3;
            uint32_t bd = smaddr(&Ks[(wc * 16 + (lane & 7) + ((lane & 16) ? 8 : 0)) * 72 +
                                     ks * 16 + (lane & 8)]);
            ldmx4(r0, r1, r2, r3, bd);
            uint32_t bf0[2] = {r0, r1}, bf1[2] = {r2, r3};
            #pragma unroll
            for (int mt = 0; mt < 2; mt++) {
                mma16816(c[mt][0], aq[mt][ks], bf0);
                mma16816(c[mt][1], aq[mt][ks], bf1);
            }
        }
        #pragma unroll
        for (int mt = 0; mt < 2; mt++)
            #pragma unroll
            for (int nt = 0; nt < 2; nt++) {
                int row = wr * 32 + mt * 16 + (lane >> 2);
                int col0 = kt * 64 + wc * 16 + nt * 8 + (lane & 3) * 2;
                #pragma unroll
                for (int h2 = 0; h2 < 2; h2++)
                    #pragma unroll
                    for (int j = 0; j < 2; j++) {
                        int col = col0 + j;
                        if (col < NT_T)
                            SPf[(row + h2 * 8) * SFLD_T + col] =
                                c[mt][nt][h2 * 2 + j] * 0.125f;
                    }
            }
    }
    __syncthreads();

    // fp32 softmax in place; probs -> half in the low half of each float row.
    #pragma unroll 1
    for (int rr = 0; rr < 8; rr++) {
        int row = warp * 8 + rr;
        float* sp = &SPf[row * SFLD_T];
        __half* hp = (__half*)sp;
        float v[9];
        float m = -1e30f;
        #pragma unroll
        for (int i2 = 0; i2 < 9; i2++) {
            int cc = lane + i2 * 32;
            v[i2] = (cc < NT_T) ? sp[cc] : -1e30f;
            m = fmaxf(m, v[i2]);
        }
        #pragma unroll
        for (int s = 16; s > 0; s >>= 1) m = fmaxf(m, __shfl_xor_sync(0xffffffffu, m, s));
        float sum = 0.f;
        #pragma unroll
        for (int i2 = 0; i2 < 9; i2++) {
            int cc = lane + i2 * 32;
            if (cc < NT_T) { v[i2] = __expf(v[i2] - m); sum += v[i2]; }
        }
        #pragma unroll
        for (int s = 16; s > 0; s >>= 1) sum += __shfl_xor_sync(0xffffffffu, sum, s);
        float inv = 1.f / sum;
        __syncwarp();
        #pragma unroll
        for (int i2 = 0; i2 < 9; i2++) {
            int cc = lane + i2 * 32;
            if (cc < NT_T) hp[cc] = __float2half_rn(v[i2] * inv);
        }
        for (int cc = NT_T + lane; cc < 272; cc += 32) hp[cc] = __float2half_rn(0.f);
    }
    __syncthreads();

    // PV: O(64x64) = P(64x272) @ V(272x64)
    float o[2][2][4];
    #pragma unroll
    for (int mt = 0; mt < 2; mt++)
        #pragma unroll
        for (int nt = 0; nt < 2; nt++)
            #pragma unroll
            for (int q = 0; q < 4; q++) o[mt][nt][q] = 0.f;
    __half* Ph = (__half*)SPf;
    const int PLD = SFLD_T * 2;
    #pragma unroll 1
    for (int ks = 0; ks < 17; ks++) {
        uint32_t ap[2][4];
        #pragma unroll
        for (int mt = 0; mt < 2; mt++) {
            uint32_t ad = smaddr(&Ph[(wr * 32 + mt * 16 + (lane & 15)) * PLD +
                                     ks * 16 + ((lane & 16) ? 8 : 0)]);
            ldmx4(ap[mt][0], ap[mt][1], ap[mt][2], ap[mt][3], ad);
        }
        uint32_t r0, r1, r2, r3;
        uint32_t bd = smaddr(&Vs[(ks * 16 + (lane & 15)) * 72 +
                                 wc * 16 + ((lane & 16) ? 8 : 0)]);
        ldmx4t(r0, r1, r2, r3, bd);
        uint32_t bf0[2] = {r0, r1}, bf1[2] = {r2, r3};
        #pragma unroll
        for (int mt = 0; mt < 2; mt++) {
            mma16816(o[mt][0], ap[mt], bf0);
            mma16816(o[mt][1], ap[mt], bf1);
        }
    }
    #pragma unroll
    for (int mt = 0; mt < 2; mt++)
        #pragma unroll
        for (int nt = 0; nt < 2; nt++) {
            int row0 = bm + wr * 32 + mt * 16 + (lane >> 2);
            int col0 = h * 64 + wc * 16 + nt * 8 + (lane & 3) * 2;
            #pragma unroll
            for (int h2 = 0; h2 < 2; h2++) {
                int row = row0 + h2 * 8;
                if (row >= NT_T) continue;
                #pragma unroll
                for (int j = 0; j < 2; j++)
                    hOT[((size_t)b * NT_T + row) * 512 + col0 + j] =
                        __float2half_rn(o[mt][nt][h2 * 2 + j]);
            }
        }
}

// ================ fused spatial Linformer attention (128 keys) ==============
#define ATNS_SMEM (11520 + 18432 + 18432 + 80 * SFLD_S * 4)
__global__ void __launch_bounds__(160, 2)
attn_s() {
    extern __shared__ char sm[];
    __half* Qs = (__half*)sm;
    __half* Ks = (__half*)(sm + 11520);
    __half* Vs = (__half*)(sm + 29952);
    float*  SPf = (float*)(sm + 48384);
    const int tid = threadIdx.x, lane = tid & 31, warp = tid >> 5;
    const int f = blockIdx.x >> 3, h = blockIdx.x & 7;
    const __half* Qg = hQKVS + (size_t)f * NT_S * (3 * DIM_C) + h * 64;
    const __half* Kc = hKC + (size_t)blockIdx.x * (KLIN_C * DH_C);
    const __half* Vc = hVC + (size_t)blockIdx.x * (KLIN_C * DH_C);
    const float4 z4 = make_float4(0.f, 0.f, 0.f, 0.f);

    #pragma unroll
    for (int i = tid; i < 640; i += 160) {                   // Q 80x64
        int r = i >> 3, s = i & 7;
        float4 v = (r < NT_S) ? *(const float4*)(Qg + (size_t)r * 1536 + s * 8) : z4;
        *(float4*)&Qs[r * 72 + s * 8] = v;
    }
    for (int i = tid; i < 1024; i += 160) {                  // K 128x64
        int r = i >> 3, s = i & 7;
        *(float4*)&Ks[r * 72 + s * 8] = *(const float4*)(Kc + (size_t)r * 64 + s * 8);
    }
    for (int i = tid; i < 1024; i += 160) {                  // V 128x64
        int r = i >> 3, s = i & 7;
        *(float4*)&Vs[r * 72 + s * 8] = *(const float4*)(Vc + (size_t)r * 64 + s * 8);
    }
    __syncthreads();

    uint32_t aq[4][4];
    #pragma unroll
    for (int ks = 0; ks < 4; ks++) {
        uint32_t ad = smaddr(&Qs[(warp * 16 + (lane & 15)) * 72 +
                                 ks * 16 + ((lane & 16) ? 8 : 0)]);
        ldmx4(aq[ks][0], aq[ks][1], aq[ks][2], aq[ks][3], ad);
    }
    float c[16][4];
    #pragma unroll
    for (int nt = 0; nt < 16; nt++)
        #pragma unroll
        for (int q = 0; q < 4; q++) c[nt][q] = 0.f;
    #pragma unroll
    for (int ks = 0; ks < 4; ks++)
        #pragma unroll
        for (int p = 0; p < 8; p++) {
            uint32_t r0, r1, r2, r3;
            uint32_t bd = smaddr(&Ks[(p * 16 + (lane & 7) + ((lane & 16) ? 8 : 0)) * 72 +
                                     ks * 16 + (lane & 8)]);
            ldmx4(r0, r1, r2, r3, bd);
            uint32_t bf0[2] = {r0, r1}, bf1[2] = {r2, r3};
            mma16816(c[2 * p], aq[ks], bf0);
            mma16816(c[2 * p + 1], aq[ks], bf1);
        }
    #pragma unroll
    for (int nt = 0; nt < 16; nt++) {
        int row = warp * 16 + (lane >> 2);
        int col0 = nt * 8 + (lane & 3) * 2;
        #pragma unroll
        for (int h2 = 0; h2 < 2; h2++)
            #pragma unroll
            for (int j = 0; j < 2; j++)
                SPf[(row + h2 * 8) * SFLD_S + col0 + j] =
                    c[nt][h2 * 2 + j] * 0.125f;
    }
    __syncthreads();

    #pragma unroll 1
    for (int rr = 0; rr < 16; rr++) {
        int row = warp * 16 + rr;
        float* sp = &SPf[row * SFLD_S];
        __half* hp = (__half*)sp;
        if (row < NT_S) {
            float v[4];
            float m = -1e30f;
            #pragma unroll
            for (int i2 = 0; i2 < 4; i2++) {
                v[i2] = sp[lane + i2 * 32];
                m = fmaxf(m, v[i2]);
            }
            #pragma unroll
            for (int s = 16; s > 0; s >>= 1) m = fmaxf(m, __shfl_xor_sync(0xffffffffu, m, s));
            float sum = 0.f;
            #pragma unroll
            for (int i2 = 0; i2 < 4; i2++) { v[i2] = __expf(v[i2] - m); sum += v[i2]; }
            #pragma unroll
            for (int s = 16; s > 0; s >>= 1) sum += __shfl_xor_sync(0xffffffffu, sum, s);
            float inv = 1.f / sum;
            __syncwarp();
            #pragma unroll
            for (int i2 = 0; i2 < 4; i2++)
                hp[lane + i2 * 32] = __float2half_rn(v[i2] * inv);
        } else {
            #pragma unroll
            for (int i2 = 0; i2 < 4; i2++) hp[lane + i2 * 32] = __float2half_rn(0.f);
        }
    }
    __syncthreads();

    float o[8][4];
    #pragma unroll
    for (int nt = 0; nt < 8; nt++)
        #pragma unroll
        for (int q = 0; q < 4; q++) o[nt][q] = 0.f;
    __half* Ph = (__half*)SPf;
    const int PLD = SFLD_S * 2;
    #pragma unroll 1
    for (int ks = 0; ks < 8; ks++) {
        uint32_t ap[4];
        uint32_t ad = smaddr(&Ph[(warp * 16 + (lane & 15)) * PLD +
                                 ks * 16 + ((lane & 16) ? 8 : 0)]);
        ldmx4(ap[0], ap[1], ap[2], ap[3], ad);
        #pragma unroll
        for (int p = 0; p < 4; p++) {
            uint32_t r0, r1, r2, r3;
            uint32_t bd = smaddr(&Vs[(ks * 16 + (lane & 15)) * 72 +
                                     p * 16 + ((lane & 16) ? 8 : 0)]);
            ldmx4t(r0, r1, r2, r3, bd);
            uint32_t bf0[2] = {r0, r1}, bf1[2] = {r2, r3};
            mma16816(o[2 * p], ap, bf0);
            mma16816(o[2 * p + 1], ap, bf1);
        }
    }
    #pragma unroll
    for (int nt = 0; nt < 8; nt++) {
        int row0 = warp * 16 + (lane >> 2);
        int col0 = h * 64 + nt * 8 + (lane & 3) * 2;
        #pragma unroll
        for (int h2 = 0; h2 < 2; h2++) {
            int row = row0 + h2 * 8;
            if (row >= NT_S) continue;
            #pragma unroll
            for (int j = 0; j < 2; j++)
                hOS[((size_t)f * NT_S + row) * 512 + col0 + j] =
                    __float2half_rn(o[nt][h2 * 2 + j]);
        }
    }
}

// =================== big fp16 GEMM: C = A(M,K) @ Bt(N,K)^T ==================
template<int EPI, int OUT>
__global__ void __launch_bounds__(256)
hgemm_big(const __half* __restrict__ A, const __half* __restrict__ Bt,
          __half* __restrict__ Ch, float* __restrict__ Cf,
          const float* __restrict__ bias, const float* __restrict__ Rf,
          int M, int N, int K, int ldc)
{
    constexpr int BK = 32, LDS_ = BK + 8;
    __shared__ __half As[2][128][LDS_];
    __shared__ __half Bs[2][128][LDS_];

    const int tid = threadIdx.x, lane = tid & 31, warp = tid >> 5;
    const int wr = warp >> 2, wc = warp & 3;
    const int bm = blockIdx.y * 128, bn = blockIdx.x * 128;
    A  += (long)bm * K;
    Bt += (long)bn * K;

    float c[4][4][4];
    #pragma unroll
    for (int i = 0; i < 4; i++)
        #pragma unroll
        for (int j = 0; j < 4; j++)
            #pragma unroll
            for (int q = 0; q < 4; q++) c[i][j][q] = 0.f;

    float4 a4[2], b4[2];
    auto loadg = [&](int t) {
        int k0 = t * BK;
        #pragma unroll
        for (int i = 0; i < 2; i++) {
            int s = tid + i * 256;
            int row = s >> 2, seg = s & 3;
            a4[i] = (bm + row < M) ? *(const float4*)(A + (long)row * K + k0 + seg * 8)
                                   : make_float4(0.f, 0.f, 0.f, 0.f);
        }
        #pragma unroll
        for (int i = 0; i < 2; i++) {
            int s = tid + i * 256;
            int row = s >> 2, seg = s & 3;
            b4[i] = *(const float4*)(Bt + (long)row * K + k0 + seg * 8);
        }
    };
    auto stores = [&](int buf) {
        #pragma unroll
        for (int i = 0; i < 2; i++) {
            int s = tid + i * 256;
            int row = s >> 2, seg = s & 3;
            *(float4*)&As[buf][row][seg * 8] = a4[i];
        }
        #pragma unroll
        for (int i = 0; i < 2; i++) {
            int s = tid + i * 256;
            int row = s >> 2, seg = s & 3;
            *(float4*)&Bs[buf][row][seg * 8] = b4[i];
        }
    };
    auto comp = [&](int cu) {
        #pragma unroll
        for (int ks = 0; ks < 2; ks++) {
            int k0 = ks * 16;
            uint32_t af[4][4], bf[4][2];
            #pragma unroll
            for (int mt = 0; mt < 4; mt++) {
                uint32_t ad = smaddr(&As[cu][wr * 64 + mt * 16 + (lane & 15)]
                                        [k0 + ((lane & 16) ? 8 : 0)]);
                ldmx4(af[mt][0], af[mt][1], af[mt][2], af[mt][3], ad);
            }
            #pragma unroll
            for (int p = 0; p < 2; p++) {
                int n0 = wc * 32 + p * 16;
                uint32_t bd = smaddr(&Bs[cu][n0 + (lane & 7) + ((lane & 16) ? 8 : 0)]
                                        [k0 + (lane & 8)]);
                uint32_t r0, r1, r2, r3;
                ldmx4(r0, r1, r2, r3, bd);
                bf[2 * p][0] = r0; bf[2 * p][1] = r1;
                bf[2 * p + 1][0] = r2; bf[2 * p + 1][1] = r3;
            }
            #pragma unroll
            for (int mt = 0; mt < 4; mt++)
                #pragma unroll
                for (int nt = 0; nt < 4; nt++)
                    mma16816(c[mt][nt], af[mt], bf[nt]);
        }
    };

    int ntl = K / BK;
    loadg(0);
    stores(0);
    __syncthreads();
    int cu = 0;
    for (int t = 0; t < ntl; t++) {
        if (t + 1 < ntl) loadg(t + 1);
        comp(cu);
        if (t + 1 < ntl) stores(cu ^ 1);
        __syncthreads();
        cu ^= 1;
    }

    #pragma unroll
    for (int mt = 0; mt < 4; mt++) {
        #pragma unroll
        for (int nt = 0; nt < 4; nt++) {
            int r0 = bm + wr * 64 + mt * 16 + (lane >> 2);
            int col = bn + wc * 32 + nt * 8 + (lane & 3) * 2;
            #pragma unroll
            for (int h = 0; h < 2; h++) {
                int r = r0 + h * 8;
                if (r >= M) continue;
                #pragma unroll
                for (int j = 0; j < 2; j++) {
                    int gc = col + j;
                    float v = c[mt][nt][h * 2 + j];
                    if constexpr (EPI == 1) {
                        v += bias[gc];
                        v = 0.5f * v * (1.f + erff(v * 0.70710678118654752f));
                    } else if constexpr (EPI == 2) {
                        v += bias[gc] + Rf[(long)r * ldc + gc];
                    } else if constexpr (EPI == 3) {
                        v += Rf[(long)r * ldc + gc];
                    }
                    if constexpr (OUT == 0) {
                        Ch[(long)r * ldc + gc] = __float2half_rn(v);
                    } else if constexpr (OUT == 1) {
                        Cf[(long)r * ldc + gc] = v;
                    } else {
                        Cf[(long)r * ldc + gc] = v;
                        Ch[(long)r * ldc + gc] = __float2half_rn(v);
                    }
                }
            }
        }
    }
}

// ============== small batched fp16 GEMM (KC/VC projection only) =============
// FIX R7: blockIdx.y row-tile offset (was missing in R5/R6 — left rows 64..127
// of each KC/VC tile unwritten).
__global__ void __launch_bounds__(128)
hgemm_sm(const __half* __restrict__ A, const __half* __restrict__ B,
         __half* __restrict__ C,
         int M, int N, int K, int lda, int ldb, int ldc,
         long siB, long siC, int NI)
{
    constexpr int BK = 16, LDS_ = BK + 8;
    __shared__ __half As[2][64][LDS_];
    __shared__ __half Bs[2][64][LDS_];

    int e = blockIdx.z;
    int o = e / NI, ii = e - o * NI;
    B += (long)o * siB + (long)ii * 64;
    const int bm = blockIdx.y * 64;               // row tile of A / C
    A += (long)bm * lda;

    const int tid = threadIdx.x, lane = tid & 31, warp = tid >> 5;
    const int wr = warp >> 1, wc = warp & 1;

    float c[2][4][4];
    #pragma unroll
    for (int i = 0; i < 2; i++)
        #pragma unroll
        for (int j = 0; j < 4; j++)
            #pragma unroll
            for (int q = 0; q < 4; q++) c[i][j][q] = 0.f;

    float4 a4, b4;
    auto loadg = [&](int t) {
        int k0 = t * BK;
        {
            int row = tid >> 1, seg = tid & 1;
            a4 = *(const float4*)(A + (long)row * lda + k0 + seg * 8);
        }
        {
            int kk = tid >> 3, nseg = tid & 7;
            b4 = *(const float4*)(B + (long)(t * BK + kk) * ldb + nseg * 8);
        }
    };
    auto stores = [&](int buf) {
        {
            int row = tid >> 1, seg = tid & 1;
            *(float4*)&As[buf][row][seg * 8] = a4;
        }
        {
            int kk = tid >> 3, nseg = tid & 7;
            const __half* hp = (const __half*)&b4;
            #pragma unroll
            for (int j = 0; j < 8; j++) Bs[buf][nseg * 8 + j][kk] = hp[j];
        }
    };
    auto comp = [&](int cu) {
        uint32_t af[2][4], bf[4][2];
        #pragma unroll
        for (int mt = 0; mt < 2; mt++) {
            uint32_t ad = smaddr(&As[cu][wr * 32 + mt * 16 + (lane & 15)]
                                    [((lane & 16) ? 8 : 0)]);
            ldmx4(af[mt][0], af[mt][1], af[mt][2], af[mt][3], ad);
        }
        #pragma unroll
        for (int p = 0; p < 2; p++) {
            int n0 = wc * 32 + p * 16;
            uint32_t bd = smaddr(&Bs[cu][n0 + (lane & 7) + ((lane & 16) ? 8 : 0)]
                                    [(lane & 8)]);
            uint32_t r0, r1, r2, r3;
            ldmx4(r0, r1, r2, r3, bd);
            bf[2 * p][0] = r0; bf[2 * p][1] = r1;
            bf[2 * p + 1][0] = r2; bf[2 * p + 1][1] = r3;
        }
        #pragma unroll
        for (int mt = 0; mt < 2; mt++)
            #pragma unroll
            for (int nt = 0; nt < 4; nt++)
                mma16816(c[mt][nt], af[mt], bf[nt]);
    };

    int ntl = K / BK;
    loadg(0);
    stores(0);
    __syncthreads();
    int cu = 0;
    for (int t = 0; t < ntl; t++) {
        if (t + 1 < ntl) loadg(t + 1);
        comp(cu);
        if (t + 1 < ntl) stores(cu ^ 1);
        __syncthreads();
        cu ^= 1;
    }

    long cbase = (long)e * siC;
    #pragma unroll
    for (int mt = 0; mt < 2; mt++) {
        #pragma unroll
        for (int nt = 0; nt < 4; nt++) {
            int r0 = bm + wr * 32 + mt * 16 + (lane >> 2);
            int col = wc * 32 + nt * 8 + (lane & 3) * 2;
            #pragma unroll
            for (int h = 0; h < 2; h++) {
                int r = r0 + h * 8;
                if (col < N) {
                    #pragma unroll
                    for (int j = 0; j < 2; j++)
                        C[cbase + (long)r * ldc + col + j] =
                            __float2half_rn(c[mt][nt][h * 2 + j]);
                }
            }
        }
    }
}

extern "C" void kernel_launch(void* const* d_in, const int* in_sizes, int n_in,
                              void* d_out, int out_size) {
    const float* x      = (const float*)d_in[0];
    const float* Wqkv_t = (const float*)d_in[1];
    const float* Wo_t   = (const float*)d_in[2];
    const float* Wqkv_s = (const float*)d_in[3];
    const float* Wo_s   = (const float*)d_in[4];
    const float* E      = (const float*)d_in[5];
    const float* W1     = (const float*)d_in[6];
    const float* b1     = (const float*)d_in[7];
    const float* W2     = (const float*)d_in[8];
    const float* b2     = (const float*)d_in[9];
    float* out = (float*)d_out;

    __half *pXT, *pQKVT, *pOT, *pZ, *pQKVS, *pEt, *pKC, *pVC, *pOS, *pY2h, *pH;
    float  *pfXT, *pfY1, *pfZ, *pfY2;
    __half *ptWqkv_t, *ptWo_t, *ptWqkv_s, *ptWo_s, *ptW1, *ptW2;
    cudaGetSymbolAddress((void**)&pXT,   hXT);
    cudaGetSymbolAddress((void**)&pfXT,  fXT);
    cudaGetSymbolAddress((void**)&pQKVT, hQKVT);
    cudaGetSymbolAddress((void**)&pOT,   hOT);
    cudaGetSymbolAddress((void**)&pfY1,  fY1);
    cudaGetSymbolAddress((void**)&pZ,    hZ);
    cudaGetSymbolAddress((void**)&pfZ,   fZ);
    cudaGetSymbolAddress((void**)&pQKVS, hQKVS);
    cudaGetSymbolAddress((void**)&pEt,   hEt);
    cudaGetSymbolAddress((void**)&pKC,   hKC);
    cudaGetSymbolAddress((void**)&pVC,   hVC);
    cudaGetSymbolAddress((void**)&pOS,   hOS);
    cudaGetSymbolAddress((void**)&pfY2,  fY2);
    cudaGetSymbolAddress((void**)&pY2h,  hY2);
    cudaGetSymbolAddress((void**)&pH,    hH);
    cudaGetSymbolAddress((void**)&ptWqkv_t, tWqkv_t);
    cudaGetSymbolAddress((void**)&ptWo_t,   tWo_t);
    cudaGetSymbolAddress((void**)&ptWqkv_s, tWqkv_s);
    cudaGetSymbolAddress((void**)&ptWo_s,   tWo_s);
    cudaGetSymbolAddress((void**)&ptW1,     tW1);
    cudaGetSymbolAddress((void**)&ptW2,     tW2);

    cudaFuncSetAttribute(attn_t, cudaFuncAttributeMaxDynamicSharedMemorySize, ATNT_SMEM);
    cudaFuncSetAttribute(attn_s, cudaFuncAttributeMaxDynamicSharedMemorySize, ATNS_SMEM);

    const int MT = BT_C * NT_T;   // 16448
    const int MS = BS_C * NT_S;   // 16640
    const int MT_T = (MT + 127) / 128;
    const int MS_T = (MS + 127) / 128;

    // 0. prep
    transpose_round<<<(3 * DIM_C * DIM_C + 255) / 256, 256>>>(ptWqkv_t, Wqkv_t, DIM_C, 3 * DIM_C);
    transpose_round<<<(DIM_C * DIM_C + 255) / 256, 256>>>(ptWo_t, Wo_t, DIM_C, DIM_C);
    transpose_round<<<(3 * DIM_C * DIM_C + 255) / 256, 256>>>(ptWqkv_s, Wqkv_s, DIM_C, 3 * DIM_C);
    transpose_round<<<(DIM_C * DIM_C + 255) / 256, 256>>>(ptWo_s, Wo_s, DIM_C, DIM_C);
    transpose_round<<<(DIM_C * DFF_C + 255) / 256, 256>>>(ptW1, W1, DIM_C, DFF_C);
    transpose_round<<<(DFF_C * DIM_C + 255) / 256, 256>>>(ptW2, W2, DFF_C, DIM_C);
    transpose_E<<<(KLIN_C * NT_S + 255) / 256, 256>>>(E);
    build_xt<<<(unsigned)(((long)BT_C * NT_T * DIM_C + 255) / 256), 256>>>(x);

    // temporal path
    hgemm_big<0, 0><<<dim3(12, MT_T), 256>>>(
        pXT, ptWqkv_t, pQKVT, nullptr, nullptr, nullptr, MT, 3 * DIM_C, DIM_C, 3 * DIM_C);
    attn_t<<<dim3(5, BT_C * HEADS_C), 256, ATNT_SMEM>>>();
    hgemm_big<3, 1><<<dim3(4, MT_T), 256>>>(
        pOT, ptWo_t, nullptr, pfY1, nullptr, pfXT, MT, DIM_C, DIM_C, DIM_C);

    // spatial path
    build_z<<<(unsigned)(((long)BS_C * NT_S * DIM_C + 255) / 256), 256>>>();
    hgemm_big<0, 0><<<dim3(12, MS_T), 256>>>(
        pZ, ptWqkv_s, pQKVS, nullptr, nullptr, nullptr, MS, 3 * DIM_C, DIM_C, 3 * DIM_C);
    hgemm_sm<<<dim3(1, 2, BS_C * HEADS_C), 128>>>(
        pEt, pQKVS + DIM_C, pKC,
        KLIN_C, DH_C, ETLD, ETLD, 3 * DIM_C, DH_C,
        (long)NT_S * 3 * DIM_C, (long)KLIN_C * DH_C, HEADS_C);
    hgemm_sm<<<dim3(1, 2, BS_C * HEADS_C), 128>>>(
        pEt, pQKVS + 2 * DIM_C, pVC,
        KLIN_C, DH_C, ETLD, ETLD, 3 * DIM_C, DH_C,
        (long)NT_S * 3 * DIM_C, (long)KLIN_C * DH_C, HEADS_C);
    attn_s<<<BS_C * HEADS_C, 160, ATNS_SMEM>>>();
    hgemm_big<3, 2><<<dim3(4, MS_T), 256>>>(
        pOS, ptWo_s, pY2h, pfY2, nullptr, pfZ, MS, DIM_C, DIM_C, DIM_C);

    // FFN
    hgemm_big<1, 0><<<dim3(8, MS_T), 256>>>(
        pY2h, ptW1, pH, nullptr, b1, nullptr, MS, DFF_C, DIM_C, DFF_C);
    hgemm_big<2, 1><<<dim3(4, MS_T), 256>>>(
        pH, ptW2, nullptr, out, b2, pfY2, MS, DIM_C, DFF_C, DIM_C);
    (void)in_sizes; (void)n_in; (void)out_size;
}

// round 11
// speedup vs baseline: 4.7125x; 1.0707x over previous
#include <cuda_runtime.h>
#include <cuda_fp16.h>
#include <math.h>
#include <stdint.h>

// ---------------------------------------------------------------------------
// TimeSformer block, sm_103 legacy-mma path. Round 9:
//   * hgemm_big: 3-stage cp.async pipeline (no register staging, no A preds
//     thanks to +64-row padded operands), 2 CTAs/SM
//   * single prep_weights kernel (6 transposes merged), KC/VC in one launch
//   * fused attention kernels unchanged from R7
// ---------------------------------------------------------------------------

#define FRAMES_C  256
#define PATCHES_C 64
#define DIM_C     512
#define HEADS_C   8
#define DH_C      64
#define DFF_C     1024
#define KLIN_C    128
#define NT_T      257
#define NT_S      65
#define BT_C      64
#define BS_C      256
#define ETLD      80
#define SFLD_T    276
#define SFLD_S    132

// ------------------------- scratch (device globals) ------------------------
__device__ __half hXT  [((size_t)BT_C * NT_T + 64) * DIM_C];
__device__ float  fXT  [(size_t)BT_C * NT_T * DIM_C];
__device__ __half hQKVT[((size_t)BT_C * NT_T + 16) * 3 * DIM_C];
__device__ __half hOT  [((size_t)BT_C * NT_T + 64) * DIM_C];
__device__ float  fY1  [(size_t)BT_C * NT_T * DIM_C];
__device__ __half hZ   [((size_t)BS_C * NT_S + 64) * DIM_C];
__device__ float  fZ   [(size_t)BS_C * NT_S * DIM_C];
__device__ __half hQKVS[((size_t)BS_C * NT_S + 16) * 3 * DIM_C];
__device__ __half hEt  [(size_t)KLIN_C * ETLD];
__device__ __half hKC  [(size_t)BS_C * HEADS_C * KLIN_C * DH_C];
__device__ __half hVC  [(size_t)BS_C * HEADS_C * KLIN_C * DH_C];
__device__ __half hOS  [((size_t)BS_C * NT_S + 64) * DIM_C];
__device__ float  fY2  [(size_t)BS_C * NT_S * DIM_C];
__device__ __half hY2  [((size_t)BS_C * NT_S + 64) * DIM_C];
__device__ __half hH   [((size_t)BS_C * NT_S + 64) * DFF_C];
__device__ __half tWqkv_t[(size_t)3 * DIM_C * DIM_C];
__device__ __half tWo_t  [(size_t)DIM_C * DIM_C];
__device__ __half tWqkv_s[(size_t)3 * DIM_C * DIM_C];
__device__ __half tWo_s  [(size_t)DIM_C * DIM_C];
__device__ __half tW1    [(size_t)DFF_C * DIM_C];
__device__ __half tW2    [(size_t)DIM_C * DFF_C];

// ------------------------------ helpers -------------------------------------
__device__ __forceinline__ uint32_t smaddr(const void* p) {
    uint32_t a;
    asm("{ .reg .u64 t; cvta.to.shared.u64 t, %1; cvt.u32.u64 %0, t; }" : "=r"(a) : "l"(p));
    return a;
}
__device__ __forceinline__ void ldmx4(uint32_t& r0, uint32_t& r1, uint32_t& r2, uint32_t& r3,
                                      uint32_t a) {
    asm volatile("ldmatrix.sync.aligned.m8n8.x4.shared.b16 {%0,%1,%2,%3}, [%4];"
                 : "=r"(r0), "=r"(r1), "=r"(r2), "=r"(r3) : "r"(a));
}
__device__ __forceinline__ void ldmx4t(uint32_t& r0, uint32_t& r1, uint32_t& r2, uint32_t& r3,
                                       uint32_t a) {
    asm volatile("ldmatrix.sync.aligned.m8n8.x4.trans.shared.b16 {%0,%1,%2,%3}, [%4];"
                 : "=r"(r0), "=r"(r1), "=r"(r2), "=r"(r3) : "r"(a));
}
__device__ __forceinline__ void mma16816(float c[4], const uint32_t a[4], const uint32_t b[2]) {
    asm volatile("mma.sync.aligned.m16n8k16.row.col.f32.f16.f16.f32 "
                 "{%0,%1,%2,%3},{%4,%5,%6,%7},{%8,%9},{%0,%1,%2,%3};"
                 : "+f"(c[0]), "+f"(c[1]), "+f"(c[2]), "+f"(c[3])
                 : "r"(a[0]), "r"(a[1]), "r"(a[2]), "r"(a[3]), "r"(b[0]), "r"(b[1]));
}
#define CPA16(dst, src) \
    asm volatile("cp.async.cg.shared.global [%0], [%1], 16;" :: "r"(dst), "l"(src) : "memory")
#define CPA_COMMIT() asm volatile("cp.async.commit_group;" ::: "memory")
#define CPA_WAIT(n)  asm volatile("cp.async.wait_group %0;" :: "n"(n) : "memory")

// ------------------------------- prep kernels -------------------------------
// all 6 weight transposes (K,N)->(N,K)+round in one launch
__global__ void prep_weights(const float* __restrict__ Wqkv_t, const float* __restrict__ Wo_t,
                             const float* __restrict__ Wqkv_s, const float* __restrict__ Wo_s,
                             const float* __restrict__ W1, const float* __restrict__ W2) {
    long i = (long)blockIdx.x * 256 + threadIdx.x;
    const long n1 = 786432, n2 = n1 + 262144, n3 = n2 + 786432,
               n4 = n3 + 262144, n5 = n4 + 524288, n6 = n5 + 524288;
    const float* src; __half* dst; long j; int K, N;
    if (i < n1)      { src = Wqkv_t; dst = tWqkv_t; j = i;      K = 512;  N = 1536; }
    else if (i < n2) { src = Wo_t;   dst = tWo_t;   j = i - n1; K = 512;  N = 512;  }
    else if (i < n3) { src = Wqkv_s; dst = tWqkv_s; j = i - n2; K = 512;  N = 1536; }
    else if (i < n4) { src = Wo_s;   dst = tWo_s;   j = i - n3; K = 512;  N = 512;  }
    else if (i < n5) { src = W1;     dst = tW1;     j = i - n4; K = 512;  N = 1024; }
    else if (i < n6) { src = W2;     dst = tW2;     j = i - n5; K = 1024; N = 512;  }
    else return;
    int k = (int)(j % K), n = (int)(j / K);
    dst[j] = __float2half_rn(src[(long)k * N + n]);
}
__global__ void build_xt(const float* __restrict__ x) {
    long idx = (long)blockIdx.x * blockDim.x + threadIdx.x;
    const long total = (long)BT_C * NT_T * DIM_C;
    if (idx >= total) return;
    int d = (int)(idx % DIM_C);
    long r = idx / DIM_C;
    int t = (int)(r % NT_T);
    int p = (int)(r / NT_T);
    float v;
    if (t == 0) v = x[d];
    else        v = x[(long)(1 + (t - 1) * PATCHES_C + p) * DIM_C + d];
    hXT[idx] = __float2half_rn(v);
    fXT[idx] = v;
}
__global__ void build_z() {
    long idx = (long)blockIdx.x * blockDim.x + threadIdx.x;
    const long total = (long)BS_C * NT_S * DIM_C;
    if (idx >= total) return;
    int d = (int)(idx % DIM_C);
    long r = idx / DIM_C;
    int s = (int)(r % NT_S);
    int f = (int)(r / NT_S);
    float v;
    if (s == 0) v = fY1[(long)(f & 63) * NT_T * DIM_C + d];
    else        v = fY1[(long)(s - 1) * NT_T * DIM_C + (long)(1 + f) * DIM_C + d];
    hZ[idx] = __float2half_rn(v);
    fZ[idx] = v;
}
__global__ void transpose_E(const float* __restrict__ E) {
    int i = blockIdx.x * blockDim.x + threadIdx.x;
    if (i >= KLIN_C * NT_S) return;
    int j = i % NT_S, kc = i / NT_S;
    hEt[kc * ETLD + j] = __float2half_rn(E[j * KLIN_C + kc]);
}

// ================= fused temporal attention (257 keys, dh=64) ===============
#define ATNT_SMEM (9216 + 9216 + 39168 + 64 * SFLD_T * 4)
__global__ void __launch_bounds__(256, 1)
attn_t() {
    extern __shared__ char sm[];
    __half* Qs = (__half*)sm;
    __half* Ks = (__half*)(sm + 9216);
    __half* Vs = (__half*)(sm + 18432);
    float*  SPf = (float*)(sm + 57600);
    const int tid = threadIdx.x, lane = tid & 31, warp = tid >> 5;
    const int bm = blockIdx.x * 64;
    const int b = blockIdx.y >> 3, h = blockIdx.y & 7;
    const __half* Qg = hQKVT + (size_t)b * NT_T * (3 * DIM_C) + h * 64;
    const __half* Kg = Qg + DIM_C;
    const __half* Vg = Qg + 2 * DIM_C;
    const float4 z4 = make_float4(0.f, 0.f, 0.f, 0.f);

    #pragma unroll
    for (int i = tid; i < 512; i += 256) {
        int r = i >> 3, s = i & 7;
        int gr = bm + r;
        float4 v = (gr < NT_T) ? *(const float4*)(Qg + (size_t)gr * 1536 + s * 8) : z4;
        *(float4*)&Qs[r * 72 + s * 8] = v;
    }
    for (int i = tid; i < 2176; i += 256) {
        int r = i >> 3, s = i & 7;
        float4 v = (r < NT_T) ? *(const float4*)(Vg + (size_t)r * 1536 + s * 8) : z4;
        *(float4*)&Vs[r * 72 + s * 8] = v;
    }
    __syncthreads();

    const int wr = warp >> 2, wc = warp & 3;
    uint32_t aq[2][4][4];
    #pragma unroll
    for (int mt = 0; mt < 2; mt++)
        #pragma unroll
        for (int ks = 0; ks < 4; ks++) {
            uint32_t ad = smaddr(&Qs[(wr * 32 + mt * 16 + (lane & 15)) * 72 +
                                     ks * 16 + ((lane & 16) ? 8 : 0)]);
            ldmx4(aq[mt][ks][0], aq[mt][ks][1], aq[mt][ks][2], aq[mt][ks][3], ad);
        }

    for (int kt = 0; kt < 5; kt++) {
        __syncthreads();
        #pragma unroll
        for (int i = tid; i < 512; i += 256) {
            int r = i >> 3, s = i & 7;
            int key = kt * 64 + r;
            float4 v = (key < NT_T) ? *(const float4*)(Kg + (size_t)key * 1536 + s * 8) : z4;
            *(float4*)&Ks[r * 72 + s * 8] = v;
        }
        __syncthreads();
        float c[2][2][4];
        #pragma unroll
        for (int mt = 0; mt < 2; mt++)
            #pragma unroll
            for (int nt = 0; nt < 2; nt++)
                #pragma unroll
                for (int q = 0; q < 4; q++) c[mt][nt][q] = 0.f;
        #pragma unroll
        for (int ks = 0; ks < 4; ks++) {
            uint32_t r0, r1, r2, r3;
            uint32_t bd = smaddr(&Ks[(wc * 16 + (lane & 7) + ((lane & 16) ? 8 : 0)) * 72 +
                                     ks * 16 + (lane & 8)]);
            ldmx4(r0, r1, r2, r3, bd);
            uint32_t bf0[2] = {r0, r1}, bf1[2] = {r2, r3};
            #pragma unroll
            for (int mt = 0; mt < 2; mt++) {
                mma16816(c[mt][0], aq[mt][ks], bf0);
                mma16816(c[mt][1], aq[mt][ks], bf1);
            }
        }
        #pragma unroll
        for (int mt = 0; mt < 2; mt++)
            #pragma unroll
            for (int nt = 0; nt < 2; nt++) {
                int row = wr * 32 + mt * 16 + (lane >> 2);
                int col0 = kt * 64 + wc * 16 + nt * 8 + (lane & 3) * 2;
                #pragma unroll
                for (int h2 = 0; h2 < 2; h2++)
                    #pragma unroll
                    for (int j = 0; j < 2; j++) {
                        int col = col0 + j;
                        if (col < NT_T)
                            SPf[(row + h2 * 8) * SFLD_T + col] =
                                c[mt][nt][h2 * 2 + j] * 0.125f;
                    }
            }
    }
    __syncthreads();

    #pragma unroll 1
    for (int rr = 0; rr < 8; rr++) {
        int row = warp * 8 + rr;
        float* sp = &SPf[row * SFLD_T];
        __half* hp = (__half*)sp;
        float v[9];
        float m = -1e30f;
        #pragma unroll
        for (int i2 = 0; i2 < 9; i2++) {
            int cc = lane + i2 * 32;
            v[i2] = (cc < NT_T) ? sp[cc] : -1e30f;
            m = fmaxf(m, v[i2]);
        }
        #pragma unroll
        for (int s = 16; s > 0; s >>= 1) m = fmaxf(m, __shfl_xor_sync(0xffffffffu, m, s));
        float sum = 0.f;
        #pragma unroll
        for (int i2 = 0; i2 < 9; i2++) {
            int cc = lane + i2 * 32;
            if (cc < NT_T) { v[i2] = __expf(v[i2] - m); sum += v[i2]; }
        }
        #pragma unroll
        for (int s = 16; s > 0; s >>= 1) sum += __shfl_xor_sync(0xffffffffu, sum, s);
        float inv = 1.f / sum;
        __syncwarp();
        #pragma unroll
        for (int i2 = 0; i2 < 9; i2++) {
            int cc = lane + i2 * 32;
            if (cc < NT_T) hp[cc] = __float2half_rn(v[i2] * inv);
        }
        for (int cc = NT_T + lane; cc < 272; cc += 32) hp[cc] = __float2half_rn(0.f);
    }
    __syncthreads();

    float o[2][2][4];
    #pragma unroll
    for (int mt = 0; mt < 2; mt++)
        #pragma unroll
        for (int nt = 0; nt < 2; nt++)
            #pragma unroll
            for (int q = 0; q < 4; q++) o[mt][nt][q] = 0.f;
    __half* Ph = (__half*)SPf;
    const int PLD = SFLD_T * 2;
    #pragma unroll 1
    for (int ks = 0; ks < 17; ks++) {
        uint32_t ap[2][4];
        #pragma unroll
        for (int mt = 0; mt < 2; mt++) {
            uint32_t ad = smaddr(&Ph[(wr * 32 + mt * 16 + (lane & 15)) * PLD +
                                     ks * 16 + ((lane & 16) ? 8 : 0)]);
            ldmx4(ap[mt][0], ap[mt][1], ap[mt][2], ap[mt][3], ad);
        }
        uint32_t r0, r1, r2, r3;
        uint32_t bd = smaddr(&Vs[(ks * 16 + (lane & 15)) * 72 +
                                 wc * 16 + ((lane & 16) ? 8 : 0)]);
        ldmx4t(r0, r1, r2, r3, bd);
        uint32_t bf0[2] = {r0, r1}, bf1[2] = {r2, r3};
        #pragma unroll
        for (int mt = 0; mt < 2; mt++) {
            mma16816(o[mt][0], ap[mt], bf0);
            mma16816(o[mt][1], ap[mt], bf1);
        }
    }
    #pragma unroll
    for (int mt = 0; mt < 2; mt++)
        #pragma unroll
        for (int nt = 0; nt < 2; nt++) {
            int row0 = bm + wr * 32 + mt * 16 + (lane >> 2);
            int col0 = h * 64 + wc * 16 + nt * 8 + (lane & 3) * 2;
            #pragma unroll
            for (int h2 = 0; h2 < 2; h2++) {
                int row = row0 + h2 * 8;
                if (row >= NT_T) continue;
                #pragma unroll
                for (int j = 0; j < 2; j++)
                    hOT[((size_t)b * NT_T + row) * 512 + col0 + j] =
                        __float2half_rn(o[mt][nt][h2 * 2 + j]);
            }
        }
}

// ================ fused spatial Linformer attention (128 keys) ==============
#define ATNS_SMEM (11520 + 18432 + 18432 + 80 * SFLD_S * 4)
__global__ void __launch_bounds__(160, 2)
attn_s() {
    extern __shared__ char sm[];
    __half* Qs = (__half*)sm;
    __half* Ks = (__half*)(sm + 11520);
    __half* Vs = (__half*)(sm + 29952);
    float*  SPf = (float*)(sm + 48384);
    const int tid = threadIdx.x, lane = tid & 31, warp = tid >> 5;
    const int f = blockIdx.x >> 3, h = blockIdx.x & 7;
    const __half* Qg = hQKVS + (size_t)f * NT_S * (3 * DIM_C) + h * 64;
    const __half* Kc = hKC + (size_t)blockIdx.x * (KLIN_C * DH_C);
    const __half* Vc = hVC + (size_t)blockIdx.x * (KLIN_C * DH_C);
    const float4 z4 = make_float4(0.f, 0.f, 0.f, 0.f);

    #pragma unroll
    for (int i = tid; i < 640; i += 160) {
        int r = i >> 3, s = i & 7;
        float4 v = (r < NT_S) ? *(const float4*)(Qg + (size_t)r * 1536 + s * 8) : z4;
        *(float4*)&Qs[r * 72 + s * 8] = v;
    }
    for (int i = tid; i < 1024; i += 160) {
        int r = i >> 3, s = i & 7;
        *(float4*)&Ks[r * 72 + s * 8] = *(const float4*)(Kc + (size_t)r * 64 + s * 8);
    }
    for (int i = tid; i < 1024; i += 160) {
        int r = i >> 3, s = i & 7;
        *(float4*)&Vs[r * 72 + s * 8] = *(const float4*)(Vc + (size_t)r * 64 + s * 8);
    }
    __syncthreads();

    uint32_t aq[4][4];
    #pragma unroll
    for (int ks = 0; ks < 4; ks++) {
        uint32_t ad = smaddr(&Qs[(warp * 16 + (lane & 15)) * 72 +
                                 ks * 16 + ((lane & 16) ? 8 : 0)]);
        ldmx4(aq[ks][0], aq[ks][1], aq[ks][2], aq[ks][3], ad);
    }
    float c[16][4];
    #pragma unroll
    for (int nt = 0; nt < 16; nt++)
        #pragma unroll
        for (int q = 0; q < 4; q++) c[nt][q] = 0.f;
    #pragma unroll
    for (int ks = 0; ks < 4; ks++)
        #pragma unroll
        for (int p = 0; p < 8; p++) {
            uint32_t r0, r1, r2, r3;
            uint32_t bd = smaddr(&Ks[(p * 16 + (lane & 7) + ((lane & 16) ? 8 : 0)) * 72 +
                                     ks * 16 + (lane & 8)]);
            ldmx4(r0, r1, r2, r3, bd);
            uint32_t bf0[2] = {r0, r1}, bf1[2] = {r2, r3};
            mma16816(c[2 * p], aq[ks], bf0);
            mma16816(c[2 * p + 1], aq[ks], bf1);
        }
    #pragma unroll
    for (int nt = 0; nt < 16; nt++) {
        int row = warp * 16 + (lane >> 2);
        int col0 = nt * 8 + (lane & 3) * 2;
        #pragma unroll
        for (int h2 = 0; h2 < 2; h2++)
            #pragma unroll
            for (int j = 0; j < 2; j++)
                SPf[(row + h2 * 8) * SFLD_S + col0 + j] =
                    c[nt][h2 * 2 + j] * 0.125f;
    }
    __syncthreads();

    #pragma unroll 1
    for (int rr = 0; rr < 16; rr++) {
        int row = warp * 16 + rr;
        float* sp = &SPf[row * SFLD_S];
        __half* hp = (__half*)sp;
        if (row < NT_S) {
            float v[4];
            float m = -1e30f;
            #pragma unroll
            for (int i2 = 0; i2 < 4; i2++) {
                v[i2] = sp[lane + i2 * 32];
                m = fmaxf(m, v[i2]);
            }
            #pragma unroll
            for (int s = 16; s > 0; s >>= 1) m = fmaxf(m, __shfl_xor_sync(0xffffffffu, m, s));
            float sum = 0.f;
            #pragma unroll
            for (int i2 = 0; i2 < 4; i2++) { v[i2] = __expf(v[i2] - m); sum += v[i2]; }
            #pragma unroll
            for (int s = 16; s > 0; s >>= 1) sum += __shfl_xor_sync(0xffffffffu, sum, s);
            float inv = 1.f / sum;
            __syncwarp();
            #pragma unroll
            for (int i2 = 0; i2 < 4; i2++)
                hp[lane + i2 * 32] = __float2half_rn(v[i2] * inv);
        } else {
            #pragma unroll
            for (int i2 = 0; i2 < 4; i2++) hp[lane + i2 * 32] = __float2half_rn(0.f);
        }
    }
    __syncthreads();

    float o[8][4];
    #pragma unroll
    for (int nt = 0; nt < 8; nt++)
        #pragma unroll
        for (int q = 0; q < 4; q++) o[nt][q] = 0.f;
    __half* Ph = (__half*)SPf;
    const int PLD = SFLD_S * 2;
    #pragma unroll 1
    for (int ks = 0; ks < 8; ks++) {
        uint32_t ap[4];
        uint32_t ad = smaddr(&Ph[(warp * 16 + (lane & 15)) * PLD +
                                 ks * 16 + ((lane & 16) ? 8 : 0)]);
        ldmx4(ap[0], ap[1], ap[2], ap[3], ad);
        #pragma unroll
        for (int p = 0; p < 4; p++) {
            uint32_t r0, r1, r2, r3;
            uint32_t bd = smaddr(&Vs[(ks * 16 + (lane & 15)) * 72 +
                                     p * 16 + ((lane & 16) ? 8 : 0)]);
            ldmx4t(r0, r1, r2, r3, bd);
            uint32_t bf0[2] = {r0, r1}, bf1[2] = {r2, r3};
            mma16816(o[2 * p], ap, bf0);
            mma16816(o[2 * p + 1], ap, bf1);
        }
    }
    #pragma unroll
    for (int nt = 0; nt < 8; nt++) {
        int row0 = warp * 16 + (lane >> 2);
        int col0 = h * 64 + nt * 8 + (lane & 3) * 2;
        #pragma unroll
        for (int h2 = 0; h2 < 2; h2++) {
            int row = row0 + h2 * 8;
            if (row >= NT_S) continue;
            #pragma unroll
            for (int j = 0; j < 2; j++)
                hOS[((size_t)f * NT_S + row) * 512 + col0 + j] =
                    __float2half_rn(o[nt][h2 * 2 + j]);
        }
    }
}

// ====== big fp16 GEMM, 3-stage cp.async: C = A(M,K) @ Bt(N,K)^T =============
// A buffers are padded to >= gridY*128 rows (pad rows zero) -> NO A predicates.
#define HGB_STAGE 20480          // per stage: A 10240B + B 10240B
#define HGB_SMEM  (3 * HGB_STAGE)

template<int EPI, int OUT>
__global__ void __launch_bounds__(256, 2)
hgemm_big(const __half* __restrict__ A, const __half* __restrict__ Bt,
          __half* __restrict__ Ch, float* __restrict__ Cf,
          const float* __restrict__ bias, const float* __restrict__ Rf,
          int M, int N, int K, int ldc)
{
    constexpr int BK = 32;
    extern __shared__ char smraw[];
    const uint32_t sb = smaddr(smraw);

    const int tid = threadIdx.x, lane = tid & 31, warp = tid >> 5;
    const int wr = warp >> 2, wc = warp & 3;
    const int bm = blockIdx.y * 128, bn = blockIdx.x * 128;
    A  += (long)bm * K;
    Bt += (long)bn * K;

    float c[4][4][4];
    #pragma unroll
    for (int i = 0; i < 4; i++)
        #pragma unroll
        for (int j = 0; j < 4; j++)
            #pragma unroll
            for (int q = 0; q < 4; q++) c[i][j][q] = 0.f;

    // row/seg for this thread's 2 chunks per matrix (16B each)
    auto prefetch = [&](int t) {
        int s = t - (t / 3) * 3;
        uint32_t ab = sb + s * HGB_STAGE;
        uint32_t bb = ab + 10240;
        int k0 = t * BK;
        #pragma unroll
        for (int i = 0; i < 2; i++) {
            int ch = tid + i * 256;
            int row = ch >> 2, seg = ch & 3;
            CPA16(ab + row * 80 + seg * 16, A + (long)row * K + k0 + seg * 8);
            CPA16(bb + row * 80 + seg * 16, Bt + (long)row * K + k0 + seg * 8);
        }
        CPA_COMMIT();
    };

    auto comp = [&](int s) {
        const __half* Asb = (const __half*)(smraw + s * HGB_STAGE);
        const __half* Bsb = (const __half*)(smraw + s * HGB_STAGE + 10240);
        #pragma unroll
        for (int ks = 0; ks < 2; ks++) {
            int k0 = ks * 16;
            uint32_t af[4][4], bf[4][2];
            #pragma unroll
            for (int mt = 0; mt < 4; mt++) {
                uint32_t ad = smaddr(Asb + (wr * 64 + mt * 16 + (lane & 15)) * 40 +
                                     k0 + ((lane & 16) ? 8 : 0));
                ldmx4(af[mt][0], af[mt][1], af[mt][2], af[mt][3], ad);
            }
            #pragma unroll
            for (int p = 0; p < 2; p++) {
                int n0 = wc * 32 + p * 16;
                uint32_t bd = smaddr(Bsb + (n0 + (lane & 7) + ((lane & 16) ? 8 : 0)) * 40 +
                                     k0 + (lane & 8));
                uint32_t r0, r1, r2, r3;
                ldmx4(r0, r1, r2, r3, bd);
                bf[2 * p][0] = r0; bf[2 * p][1] = r1;
                bf[2 * p + 1][0] = r2; bf[2 * p + 1][1] = r3;
            }
            #pragma unroll
            for (int mt = 0; mt < 4; mt++)
                #pragma unroll
                for (int nt = 0; nt < 4; nt++)
                    mma16816(c[mt][nt], af[mt], bf[nt]);
        }
    };

    const int ntl = K / BK;
    prefetch(0);
    prefetch(1);
    CPA_WAIT(1);
    __syncthreads();
    int s = 0;
    for (int t = 0; t < ntl; t++) {
        comp(s);
        if (t + 2 < ntl) { prefetch(t + 2); CPA_WAIT(1); }
        else             { CPA_WAIT(0); }
        __syncthreads();
        s = (s == 2) ? 0 : s + 1;
    }

    #pragma unroll
    for (int mt = 0; mt < 4; mt++) {
        #pragma unroll
        for (int nt = 0; nt < 4; nt++) {
            int r0 = bm + wr * 64 + mt * 16 + (lane >> 2);
            int col = bn + wc * 32 + nt * 8 + (lane & 3) * 2;
            #pragma unroll
            for (int h = 0; h < 2; h++) {
                int r = r0 + h * 8;
                if (r >= M) continue;
                #pragma unroll
                for (int j = 0; j < 2; j++) {
                    int gc = col + j;
                    float v = c[mt][nt][h * 2 + j];
                    if constexpr (EPI == 1) {
                        v += bias[gc];
                        v = 0.5f * v * (1.f + erff(v * 0.70710678118654752f));
                    } else if constexpr (EPI == 2) {
                        v += bias[gc] + Rf[(long)r * ldc + gc];
                    } else if constexpr (EPI == 3) {
                        v += Rf[(long)r * ldc + gc];
                    }
                    if constexpr (OUT == 0) {
                        Ch[(long)r * ldc + gc] = __float2half_rn(v);
                    } else if constexpr (OUT == 1) {
                        Cf[(long)r * ldc + gc] = v;
                    } else {
                        Cf[(long)r * ldc + gc] = v;
                        Ch[(long)r * ldc + gc] = __float2half_rn(v);
                    }
                }
            }
        }
    }
}

// ============== small batched fp16 GEMM (KC + VC in one launch) =============
__global__ void __launch_bounds__(128)
hgemm_kv(const __half* __restrict__ Et, const __half* __restrict__ QKVS,
         __half* __restrict__ KC, __half* __restrict__ VC)
{
    constexpr int BK = 16, LDS_ = BK + 8;
    __shared__ __half As[2][64][LDS_];
    __shared__ __half Bs[2][64][LDS_];

    const int lda = ETLD, ldb = 3 * DIM_C, ldc = DH_C, K = ETLD;
    int e = blockIdx.z;
    bool isV = e >= BS_C * HEADS_C;
    int eb = isV ? e - BS_C * HEADS_C : e;
    int o = eb >> 3, ii = eb & 7;
    const __half* B = QKVS + (isV ? 2 * DIM_C : DIM_C) +
                      (long)o * ((long)NT_S * 3 * DIM_C) + ii * 64;
    __half* C = (isV ? VC : KC) + (long)eb * (KLIN_C * DH_C);
    const int bm = blockIdx.y * 64;
    const __half* A = Et + (long)bm * lda;

    const int tid = threadIdx.x, lane = tid & 31, warp = tid >> 5;
    const int wr = warp >> 1, wc = warp & 1;

    float c[2][4][4];
    #pragma unroll
    for (int i = 0; i < 2; i++)
        #pragma unroll
        for (int j = 0; j < 4; j++)
            #pragma unroll
            for (int q = 0; q < 4; q++) c[i][j][q] = 0.f;

    float4 a4, b4;
    auto loadg = [&](int t) {
        int k0 = t * BK;
        {
            int row = tid >> 1, seg = tid & 1;
            a4 = *(const float4*)(A + (long)row * lda + k0 + seg * 8);
        }
        {
            int kk = tid >> 3, nseg = tid & 7;
            b4 = *(const float4*)(B + (long)(t * BK + kk) * ldb + nseg * 8);
        }
    };
    auto stores = [&](int buf) {
        {
            int row = tid >> 1, seg = tid & 1;
            *(float4*)&As[buf][row][seg * 8] = a4;
        }
        {
            int kk = tid >> 3, nseg = tid & 7;
            const __half* hp = (const __half*)&b4;
            #pragma unroll
            for (int j = 0; j < 8; j++) Bs[buf][nseg * 8 + j][kk] = hp[j];
        }
    };
    auto comp = [&](int cu) {
        uint32_t af[2][4], bf[4][2];
        #pragma unroll
        for (int mt = 0; mt < 2; mt++) {
            uint32_t ad = smaddr(&As[cu][wr * 32 + mt * 16 + (lane & 15)]
                                    [((lane & 16) ? 8 : 0)]);
            ldmx4(af[mt][0], af[mt][1], af[mt][2], af[mt][3], ad);
        }
        #pragma unroll
        for (int p = 0; p < 2; p++) {
            int n0 = wc * 32 + p * 16;
            uint32_t bd = smaddr(&Bs[cu][n0 + (lane & 7) + ((lane & 16) ? 8 : 0)]
                                    [(lane & 8)]);
            uint32_t r0, r1, r2, r3;
            ldmx4(r0, r1, r2, r3, bd);
            bf[2 * p][0] = r0; bf[2 * p][1] = r1;
            bf[2 * p + 1][0] = r2; bf[2 * p + 1][1] = r3;
        }
        #pragma unroll
        for (int mt = 0; mt < 2; mt++)
            #pragma unroll
            for (int nt = 0; nt < 4; nt++)
                mma16816(c[mt][nt], af[mt], bf[nt]);
    };

    int ntl = K / BK;
    loadg(0);
    stores(0);
    __syncthreads();
    int cu = 0;
    for (int t = 0; t < ntl; t++) {
        if (t + 1 < ntl) loadg(t + 1);
        comp(cu);
        if (t + 1 < ntl) stores(cu ^ 1);
        __syncthreads();
        cu ^= 1;
    }

    #pragma unroll
    for (int mt = 0; mt < 2; mt++) {
        #pragma unroll
        for (int nt = 0; nt < 4; nt++) {
            int r0 = bm + wr * 32 + mt * 16 + (lane >> 2);
            int col = wc * 32 + nt * 8 + (lane & 3) * 2;
            #pragma unroll
            for (int h = 0; h < 2; h++) {
                int r = r0 + h * 8;
                if (col < DH_C) {
                    #pragma unroll
                    for (int j = 0; j < 2; j++)
                        C[(long)r * ldc + col + j] =
                            __float2half_rn(c[mt][nt][h * 2 + j]);
                }
            }
        }
    }
}

extern "C" void kernel_launch(void* const* d_in, const int* in_sizes, int n_in,
                              void* d_out, int out_size) {
    const float* x      = (const float*)d_in[0];
    const float* Wqkv_t = (const float*)d_in[1];
    const float* Wo_t   = (const float*)d_in[2];
    const float* Wqkv_s = (const float*)d_in[3];
    const float* Wo_s   = (const float*)d_in[4];
    const float* E      = (const float*)d_in[5];
    const float* W1     = (const float*)d_in[6];
    const float* b1     = (const float*)d_in[7];
    const float* W2     = (const float*)d_in[8];
    const float* b2     = (const float*)d_in[9];
    float* out = (float*)d_out;

    __half *pXT, *pQKVT, *pOT, *pZ, *pQKVS, *pEt, *pKC, *pVC, *pOS, *pY2h, *pH;
    float  *pfXT, *pfY1, *pfZ, *pfY2;
    __half *ptWqkv_t, *ptWo_t, *ptWqkv_s, *ptWo_s, *ptW1, *ptW2;
    cudaGetSymbolAddress((void**)&pXT,   hXT);
    cudaGetSymbolAddress((void**)&pfXT,  fXT);
    cudaGetSymbolAddress((void**)&pQKVT, hQKVT);
    cudaGetSymbolAddress((void**)&pOT,   hOT);
    cudaGetSymbolAddress((void**)&pfY1,  fY1);
    cudaGetSymbolAddress((void**)&pZ,    hZ);
    cudaGetSymbolAddress((void**)&pfZ,   fZ);
    cudaGetSymbolAddress((void**)&pQKVS, hQKVS);
    cudaGetSymbolAddress((void**)&pEt,   hEt);
    cudaGetSymbolAddress((void**)&pKC,   hKC);
    cudaGetSymbolAddress((void**)&pVC,   hVC);
    cudaGetSymbolAddress((void**)&pOS,   hOS);
    cudaGetSymbolAddress((void**)&pfY2,  fY2);
    cudaGetSymbolAddress((void**)&pY2h,  hY2);
    cudaGetSymbolAddress((void**)&pH,    hH);
    cudaGetSymbolAddress((void**)&ptWqkv_t, tWqkv_t);
    cudaGetSymbolAddress((void**)&ptWo_t,   tWo_t);
    cudaGetSymbolAddress((void**)&ptWqkv_s, tWqkv_s);
    cudaGetSymbolAddress((void**)&ptWo_s,   tWo_s);
    cudaGetSymbolAddress((void**)&ptW1,     tW1);
    cudaGetSymbolAddress((void**)&ptW2,     tW2);

    cudaFuncSetAttribute(attn_t, cudaFuncAttributeMaxDynamicSharedMemorySize, ATNT_SMEM);
    cudaFuncSetAttribute(attn_s, cudaFuncAttributeMaxDynamicSharedMemorySize, ATNS_SMEM);
    cudaFuncSetAttribute(hgemm_big<0, 0>, cudaFuncAttributeMaxDynamicSharedMemorySize, HGB_SMEM);
    cudaFuncSetAttribute(hgemm_big<1, 0>, cudaFuncAttributeMaxDynamicSharedMemorySize, HGB_SMEM);
    cudaFuncSetAttribute(hgemm_big<2, 1>, cudaFuncAttributeMaxDynamicSharedMemorySize, HGB_SMEM);
    cudaFuncSetAttribute(hgemm_big<3, 1>, cudaFuncAttributeMaxDynamicSharedMemorySize, HGB_SMEM);
    cudaFuncSetAttribute(hgemm_big<3, 2>, cudaFuncAttributeMaxDynamicSharedMemorySize, HGB_SMEM);

    const int MT = BT_C * NT_T;   // 16448
    const int MS = BS_C * NT_S;   // 16640
    const int MT_T = (MT + 127) / 128;   // 129 (A pads cover 64 extra rows)
    const int MS_T = (MS + 127) / 128;   // 130 (exact)

    // 0. prep
    {
        long total = 786432L + 262144 + 786432 + 262144 + 524288 + 524288;
        prep_weights<<<(unsigned)((total + 255) / 256), 256>>>(
            Wqkv_t, Wo_t, Wqkv_s, Wo_s, W1, W2);
    }
    transpose_E<<<(KLIN_C * NT_S + 255) / 256, 256>>>(E);
    build_xt<<<(unsigned)(((long)BT_C * NT_T * DIM_C + 255) / 256), 256>>>(x);

    // temporal path
    hgemm_big<0, 0><<<dim3(12, MT_T), 256, HGB_SMEM>>>(
        pXT, ptWqkv_t, pQKVT, nullptr, nullptr, nullptr, MT, 3 * DIM_C, DIM_C, 3 * DIM_C);
    attn_t<<<dim3(5, BT_C * HEADS_C), 256, ATNT_SMEM>>>();
    hgemm_big<3, 1><<<dim3(4, MT_T), 256, HGB_SMEM>>>(
        pOT, ptWo_t, nullptr, pfY1, nullptr, pfXT, MT, DIM_C, DIM_C, DIM_C);

    // spatial path
    build_z<<<(unsigned)(((long)BS_C * NT_S * DIM_C + 255) / 256), 256>>>();
    hgemm_big<0, 0><<<dim3(12, MS_T), 256, HGB_SMEM>>>(
        pZ, ptWqkv_s, pQKVS, nullptr, nullptr, nullptr, MS, 3 * DIM_C, DIM_C, 3 * DIM_C);
    hgemm_kv<<<dim3(1, 2, 2 * BS_C * HEADS_C), 128>>>(pEt, pQKVS, pKC, pVC);
    attn_s<<<BS_C * HEADS_C, 160, ATNS_SMEM>>>();
    hgemm_big<3, 2><<<dim3(4, MS_T), 256, HGB_SMEM>>>(
        pOS, ptWo_s, pY2h, pfY2, nullptr, pfZ, MS, DIM_C, DIM_C, DIM_C);

    // FFN
    hgemm_big<1, 0><<<dim3(8, MS_T), 256, HGB_SMEM>>>(
        pY2h, ptW1, pH, nullptr, b1, nullptr, MS, DFF_C, DIM_C, DFF_C);
    hgemm_big<2, 1><<<dim3(4, MS_T), 256, HGB_SMEM>>>(
        pH, ptW2, nullptr, out, b2, pfY2, MS, DIM_C, DFF_C, DIM_C);
    (void)in_sizes; (void)n_in; (void)out_size;
}